// round 10
// baseline (speedup 1.0000x reference)
#include <cuda_runtime.h>
#include <cstdint>

#define D_MODEL 1024
#define NUM_HEADS 16
#define DEPTH 64
#define BATCH 2
#define SEQ 2048
#define MTOT (BATCH * SEQ)            // 4096 rows
#define OUT_ELEMS ((long long)BATCH * SEQ * D_MODEL)          // 4,194,304
#define ATTN_ELEMS ((long long)BATCH * NUM_HEADS * SEQ * SEQ) // 134,217,728

// Scratch (no allocations allowed) — 4 x 16 MB
__device__ float g_Q[MTOT * D_MODEL];
__device__ float g_K[MTOT * D_MODEL];
__device__ float g_V[MTOT * D_MODEL];
__device__ float g_ctx[MTOT * D_MODEL];

// ---------------------------------------------------------------------------
// Tiled fp32 GEMM: C[M,N] = A[M,K] @ W[K,N] + bias[N]
// 128x128 tile, TK=8, 256 threads, 8x8 accum per thread.
// ---------------------------------------------------------------------------
#define GTK 8
__global__ __launch_bounds__(256) void gemm_bias_kernel(
    const float* __restrict__ A, const float* __restrict__ W,
    const float* __restrict__ bias, float* __restrict__ C,
    int M, int N, int K)
{
    __shared__ float As[GTK][132];   // padded, stored transposed
    __shared__ float Bs[GTK][128];

    const int tid = threadIdx.x;
    const int bm = blockIdx.y * 128;
    const int bn = blockIdx.x * 128;
    const int tx = tid & 15;         // n direction
    const int ty = tid >> 4;         // m direction

    float acc[8][8];
#pragma unroll
    for (int i = 0; i < 8; i++)
#pragma unroll
        for (int j = 0; j < 8; j++) acc[i][j] = 0.f;

    const int ar = tid >> 1;              // 0..127 (A row within tile)
    const int akc = (tid & 1) * 4;        // 0 or 4 (A k offset)
    const int bkr = tid >> 5;             // 0..7   (B k row)
    const int bnc = (tid & 31) * 4;       // 0..124 (B n offset)

    for (int k0 = 0; k0 < K; k0 += GTK) {
        {
            float4 v = *reinterpret_cast<const float4*>(
                A + (size_t)(bm + ar) * K + k0 + akc);
            As[akc + 0][ar] = v.x;
            As[akc + 1][ar] = v.y;
            As[akc + 2][ar] = v.z;
            As[akc + 3][ar] = v.w;
        }
        {
            float4 v = *reinterpret_cast<const float4*>(
                W + (size_t)(k0 + bkr) * N + bn + bnc);
            *reinterpret_cast<float4*>(&Bs[bkr][bnc]) = v;
        }
        __syncthreads();

#pragma unroll
        for (int kk = 0; kk < GTK; kk++) {
            float a[8], b[8];
#pragma unroll
            for (int i = 0; i < 8; i++) a[i] = As[kk][ty * 8 + i];
#pragma unroll
            for (int j = 0; j < 8; j++) b[j] = Bs[kk][tx * 8 + j];
#pragma unroll
            for (int i = 0; i < 8; i++)
#pragma unroll
                for (int j = 0; j < 8; j++) acc[i][j] += a[i] * b[j];
        }
        __syncthreads();
    }

#pragma unroll
    for (int i = 0; i < 8; i++) {
        int m = bm + ty * 8 + i;
#pragma unroll
        for (int j = 0; j < 8; j += 4) {
            int n = bn + tx * 8 + j;
            float4 o;
            o.x = acc[i][j + 0] + bias[n + 0];
            o.y = acc[i][j + 1] + bias[n + 1];
            o.z = acc[i][j + 2] + bias[n + 2];
            o.w = acc[i][j + 3] + bias[n + 3];
            *reinterpret_cast<float4*>(C + (size_t)m * N + n) = o;
        }
    }
}

// ---------------------------------------------------------------------------
// Register-tiled causal attention. One block per (b, h, 64-row q-tile).
// 128 threads; each thread owns an 8x4 fragment of S / P / ctx.
// Writes unnormalized exp(logit) to attn, accumulates row sums in regs,
// rescales its own attn rows (and zeros the masked region) in an epilogue.
// ---------------------------------------------------------------------------
__global__ __launch_bounds__(128, 4) void attn_pass1(
    const float* __restrict__ Qp, const float* __restrict__ Kp,
    const float* __restrict__ Vp, float* __restrict__ attn,
    float* __restrict__ ctx)
{
    __shared__ float Qs[64][65];
    __shared__ float KVs[64][65];
    __shared__ float Ps[64][65];
    __shared__ float invs[64];

    const int tid   = threadIdx.x;
    const int qt    = (int)gridDim.x - 1 - (int)blockIdx.x;   // largest tile first
    const int h     = blockIdx.y & (NUM_HEADS - 1);
    const int b     = blockIdx.y >> 4;
    const int qbase = qt * 64;

    const int tx = tid & 15;
    const int ty = tid >> 4;            // 0..7
    const int r0 = ty * 8;
    const int n0 = tx * 4;

    const size_t qkvBase  = (size_t)b * SEQ * D_MODEL + (size_t)h * DEPTH;
    const size_t attnRow0 = (((size_t)b * NUM_HEADS + h) * SEQ + qbase) * SEQ;

    // Load Q tile [64 rows][64 d]
#pragma unroll
    for (int it = 0; it < 8; it++) {
        int idx = tid + it * 128;
        int r  = idx >> 4;
        int d4 = (idx & 15) * 4;
        float4 v = *reinterpret_cast<const float4*>(
            Qp + qkvBase + (size_t)(qbase + r) * D_MODEL + d4);
        Qs[r][d4 + 0] = v.x; Qs[r][d4 + 1] = v.y;
        Qs[r][d4 + 2] = v.z; Qs[r][d4 + 3] = v.w;
    }

    float ctxa[8][4];
    float rpart[8];
#pragma unroll
    for (int i = 0; i < 8; i++) {
        rpart[i] = 0.f;
#pragma unroll
        for (int j = 0; j < 4; j++) ctxa[i][j] = 0.f;
    }

    __syncthreads();

    for (int c = 0; c <= qt; c++) {
        const int kbase = c * 64;

        // Load K chunk [64 rows][64 d]
#pragma unroll
        for (int it = 0; it < 8; it++) {
            int idx = tid + it * 128;
            int r  = idx >> 4;
            int d4 = (idx & 15) * 4;
            float4 v = *reinterpret_cast<const float4*>(
                Kp + qkvBase + (size_t)(kbase + r) * D_MODEL + d4);
            KVs[r][d4 + 0] = v.x; KVs[r][d4 + 1] = v.y;
            KVs[r][d4 + 2] = v.z; KVs[r][d4 + 3] = v.w;
        }
        __syncthreads();

        // S = Q @ K^T  (8x4 fragment per thread)
        float s[8][4];
#pragma unroll
        for (int i = 0; i < 8; i++)
#pragma unroll
            for (int j = 0; j < 4; j++) s[i][j] = 0.f;

#pragma unroll 4
        for (int k = 0; k < 64; k++) {
            float a[8], bb[4];
#pragma unroll
            for (int i = 0; i < 8; i++) a[i] = Qs[r0 + i][k];
#pragma unroll
            for (int j = 0; j < 4; j++) bb[j] = KVs[n0 + j][k];
#pragma unroll
            for (int i = 0; i < 8; i++)
#pragma unroll
                for (int j = 0; j < 4; j++) s[i][j] += a[i] * bb[j];
        }

        // P = exp(S/8) with causal mask on the diagonal tile.
        const bool diag = (c == qt);
#pragma unroll
        for (int i = 0; i < 8; i++) {
            float p[4];
#pragma unroll
            for (int j = 0; j < 4; j++) {
                float e = __expf(s[i][j] * 0.125f);
                if (diag && (n0 + j) > (r0 + i)) e = 0.f;
                p[j] = e;
                rpart[i] += e;
                Ps[r0 + i][n0 + j] = e;
            }
            if (attn) {
                float4 pv; pv.x = p[0]; pv.y = p[1]; pv.z = p[2]; pv.w = p[3];
                *reinterpret_cast<float4*>(
                    attn + attnRow0 + (size_t)(r0 + i) * SEQ + kbase + n0) = pv;
            }
        }
        __syncthreads();   // done reading K, Ps fully written

        // Load V chunk [64 k][64 d]
#pragma unroll
        for (int it = 0; it < 8; it++) {
            int idx = tid + it * 128;
            int r  = idx >> 4;
            int d4 = (idx & 15) * 4;
            float4 v = *reinterpret_cast<const float4*>(
                Vp + qkvBase + (size_t)(kbase + r) * D_MODEL + d4);
            KVs[r][d4 + 0] = v.x; KVs[r][d4 + 1] = v.y;
            KVs[r][d4 + 2] = v.z; KVs[r][d4 + 3] = v.w;
        }
        __syncthreads();

        // ctx += P @ V
#pragma unroll 4
        for (int k = 0; k < 64; k++) {
            float a[8], bb[4];
#pragma unroll
            for (int i = 0; i < 8; i++) a[i] = Ps[r0 + i][k];
#pragma unroll
            for (int j = 0; j < 4; j++) bb[j] = KVs[k][n0 + j];
#pragma unroll
            for (int i = 0; i < 8; i++)
#pragma unroll
                for (int j = 0; j < 4; j++) ctxa[i][j] += a[i] * bb[j];
        }
        __syncthreads();   // before KVs/Ps reuse next chunk
    }

    // Reduce row sums across the 16 thread-columns (reuse Ps)
#pragma unroll
    for (int i = 0; i < 8; i++) Ps[r0 + i][tx] = rpart[i];
    __syncthreads();
    if (tid < 64) {
        float sm = 0.f;
#pragma unroll
        for (int x = 0; x < 16; x++) sm += Ps[tid][x];
        invs[tid] = 1.0f / sm;
    }
    __syncthreads();

    // Write normalized ctx: ctx[b, q, h*64 + d]
#pragma unroll
    for (int i = 0; i < 8; i++) {
        float inv = invs[r0 + i];
        float4 v;
        v.x = ctxa[i][0] * inv; v.y = ctxa[i][1] * inv;
        v.z = ctxa[i][2] * inv; v.w = ctxa[i][3] * inv;
        *reinterpret_cast<float4*>(
            ctx + qkvBase + (size_t)(qbase + r0 + i) * D_MODEL + n0) = v;
    }

    // Epilogue: rescale this block's attn rows; zero the masked region.
    if (attn) {
        for (int c = 0; c < SEQ / 64; c++) {
            const int kbase = c * 64;
            if (c <= qt) {
#pragma unroll
                for (int it = 0; it < 8; it++) {
                    int idx = tid + it * 128;
                    int r  = idx >> 4;
                    int d4 = (idx & 15) * 4;
                    float inv = invs[r];
                    float4* p = reinterpret_cast<float4*>(
                        attn + attnRow0 + (size_t)r * SEQ + kbase + d4);
                    float4 v = *p;
                    v.x *= inv; v.y *= inv; v.z *= inv; v.w *= inv;
                    *p = v;
                }
            } else {
                const float4 z = {0.f, 0.f, 0.f, 0.f};
#pragma unroll
                for (int it = 0; it < 8; it++) {
                    int idx = tid + it * 128;
                    int r  = idx >> 4;
                    int d4 = (idx & 15) * 4;
                    *reinterpret_cast<float4*>(
                        attn + attnRow0 + (size_t)r * SEQ + kbase + d4) = z;
                }
            }
        }
    }
}

// ---------------------------------------------------------------------------
extern "C" void kernel_launch(void* const* d_in, const int* in_sizes, int n_in,
                              void* d_out, int out_size)
{
    const float* q  = (const float*)d_in[0];
    const float* k  = (const float*)d_in[1];
    const float* v  = (const float*)d_in[2];
    // d_in[3] is the mask — causal structure applied analytically.
    const float* wq = (const float*)d_in[4];
    const float* bq = (const float*)d_in[5];
    const float* wk = (const float*)d_in[6];
    const float* bk = (const float*)d_in[7];
    const float* wv = (const float*)d_in[8];
    const float* bv = (const float*)d_in[9];
    const float* wo = (const float*)d_in[10];
    const float* bo = (const float*)d_in[11];

    float* out = (float*)d_out;
    float* attn = nullptr;
    if ((long long)out_size >= OUT_ELEMS + ATTN_ELEMS) {
        attn = out + OUT_ELEMS;
    }

    float *Qs, *Ks, *Vs, *Cs;
    cudaGetSymbolAddress((void**)&Qs, g_Q);
    cudaGetSymbolAddress((void**)&Ks, g_K);
    cudaGetSymbolAddress((void**)&Vs, g_V);
    cudaGetSymbolAddress((void**)&Cs, g_ctx);

    dim3 ggrid(D_MODEL / 128, MTOT / 128);   // (8, 32)
    gemm_bias_kernel<<<ggrid, 256>>>(q, wq, bq, Qs, MTOT, D_MODEL, D_MODEL);
    gemm_bias_kernel<<<ggrid, 256>>>(k, wk, bk, Ks, MTOT, D_MODEL, D_MODEL);
    gemm_bias_kernel<<<ggrid, 256>>>(v, wv, bv, Vs, MTOT, D_MODEL, D_MODEL);

    attn_pass1<<<dim3(SEQ / 64, BATCH * NUM_HEADS), 128>>>(Qs, Ks, Vs, attn, Cs);

    gemm_bias_kernel<<<ggrid, 256>>>(Cs, wo, bo, out, MTOT, D_MODEL, D_MODEL);
}

// round 11
// speedup vs baseline: 1.0453x; 1.0453x over previous
#include <cuda_runtime.h>
#include <cstdint>

#define D_MODEL 1024
#define NUM_HEADS 16
#define DEPTH 64
#define BATCH 2
#define SEQ 2048
#define MTOT (BATCH * SEQ)            // 4096 rows
#define OUT_ELEMS ((long long)BATCH * SEQ * D_MODEL)          // 4,194,304
#define ATTN_ELEMS ((long long)BATCH * NUM_HEADS * SEQ * SEQ) // 134,217,728

// Scratch (no allocations allowed) — 4 x 16 MB
__device__ float g_Q[MTOT * D_MODEL];
__device__ float g_K[MTOT * D_MODEL];
__device__ float g_V[MTOT * D_MODEL];
__device__ float g_ctx[MTOT * D_MODEL];

// ---------------------------------------------------------------------------
// Tiled fp32 GEMM: C[M,N] = A[M,K] @ W[K,N] + bias[N]
// 128x128 tile, TK=8, 256 threads, 8x8 accum per thread.
// ---------------------------------------------------------------------------
#define GTK 8
__global__ __launch_bounds__(256) void gemm_bias_kernel(
    const float* __restrict__ A, const float* __restrict__ W,
    const float* __restrict__ bias, float* __restrict__ C,
    int M, int N, int K)
{
    __shared__ float As[GTK][132];   // padded, stored transposed
    __shared__ float Bs[GTK][128];

    const int tid = threadIdx.x;
    const int bm = blockIdx.y * 128;
    const int bn = blockIdx.x * 128;
    const int tx = tid & 15;         // n direction
    const int ty = tid >> 4;         // m direction

    float acc[8][8];
#pragma unroll
    for (int i = 0; i < 8; i++)
#pragma unroll
        for (int j = 0; j < 8; j++) acc[i][j] = 0.f;

    const int ar = tid >> 1;              // 0..127 (A row within tile)
    const int akc = (tid & 1) * 4;        // 0 or 4 (A k offset)
    const int bkr = tid >> 5;             // 0..7   (B k row)
    const int bnc = (tid & 31) * 4;       // 0..124 (B n offset)

    for (int k0 = 0; k0 < K; k0 += GTK) {
        {
            float4 v = *reinterpret_cast<const float4*>(
                A + (size_t)(bm + ar) * K + k0 + akc);
            As[akc + 0][ar] = v.x;
            As[akc + 1][ar] = v.y;
            As[akc + 2][ar] = v.z;
            As[akc + 3][ar] = v.w;
        }
        {
            float4 v = *reinterpret_cast<const float4*>(
                W + (size_t)(k0 + bkr) * N + bn + bnc);
            *reinterpret_cast<float4*>(&Bs[bkr][bnc]) = v;
        }
        __syncthreads();

#pragma unroll
        for (int kk = 0; kk < GTK; kk++) {
            float a[8], b[8];
#pragma unroll
            for (int i = 0; i < 8; i++) a[i] = As[kk][ty * 8 + i];
#pragma unroll
            for (int j = 0; j < 8; j++) b[j] = Bs[kk][tx * 8 + j];
#pragma unroll
            for (int i = 0; i < 8; i++)
#pragma unroll
                for (int j = 0; j < 8; j++) acc[i][j] += a[i] * b[j];
        }
        __syncthreads();
    }

#pragma unroll
    for (int i = 0; i < 8; i++) {
        int m = bm + ty * 8 + i;
#pragma unroll
        for (int j = 0; j < 8; j += 4) {
            int n = bn + tx * 8 + j;
            float4 o;
            o.x = acc[i][j + 0] + bias[n + 0];
            o.y = acc[i][j + 1] + bias[n + 1];
            o.z = acc[i][j + 2] + bias[n + 2];
            o.w = acc[i][j + 3] + bias[n + 3];
            *reinterpret_cast<float4*>(C + (size_t)m * N + n) = o;
        }
    }
}

// ---------------------------------------------------------------------------
// Register-tiled causal attention. One block per (b, h, 64-row q-tile).
// 128 threads; each thread owns an 8x4 fragment of S / P / ctx.
// Writes unnormalized exp(logit) to attn, accumulates row sums in regs,
// rescales its own attn rows (and zeros the masked region) in an epilogue.
// ---------------------------------------------------------------------------
__global__ __launch_bounds__(128, 4) void attn_pass1(
    const float* __restrict__ Qp, const float* __restrict__ Kp,
    const float* __restrict__ Vp, float* __restrict__ attn,
    float* __restrict__ ctx)
{
    __shared__ float Qs[64][65];
    __shared__ float KVs[64][65];
    __shared__ float Ps[64][65];
    __shared__ float invs[64];

    const int tid   = threadIdx.x;
    const int qt    = (int)gridDim.x - 1 - (int)blockIdx.x;   // largest tile first
    const int h     = blockIdx.y & (NUM_HEADS - 1);
    const int b     = blockIdx.y >> 4;
    const int qbase = qt * 64;

    const int tx = tid & 15;
    const int ty = tid >> 4;            // 0..7
    const int r0 = ty * 8;
    const int n0 = tx * 4;

    const size_t qkvBase  = (size_t)b * SEQ * D_MODEL + (size_t)h * DEPTH;
    const size_t attnRow0 = (((size_t)b * NUM_HEADS + h) * SEQ + qbase) * SEQ;

    // Load Q tile [64 rows][64 d]
#pragma unroll
    for (int it = 0; it < 8; it++) {
        int idx = tid + it * 128;
        int r  = idx >> 4;
        int d4 = (idx & 15) * 4;
        float4 v = *reinterpret_cast<const float4*>(
            Qp + qkvBase + (size_t)(qbase + r) * D_MODEL + d4);
        Qs[r][d4 + 0] = v.x; Qs[r][d4 + 1] = v.y;
        Qs[r][d4 + 2] = v.z; Qs[r][d4 + 3] = v.w;
    }

    float ctxa[8][4];
    float rpart[8];
#pragma unroll
    for (int i = 0; i < 8; i++) {
        rpart[i] = 0.f;
#pragma unroll
        for (int j = 0; j < 4; j++) ctxa[i][j] = 0.f;
    }

    __syncthreads();

    for (int c = 0; c <= qt; c++) {
        const int kbase = c * 64;

        // Load K chunk [64 rows][64 d]
#pragma unroll
        for (int it = 0; it < 8; it++) {
            int idx = tid + it * 128;
            int r  = idx >> 4;
            int d4 = (idx & 15) * 4;
            float4 v = *reinterpret_cast<const float4*>(
                Kp + qkvBase + (size_t)(kbase + r) * D_MODEL + d4);
            KVs[r][d4 + 0] = v.x; KVs[r][d4 + 1] = v.y;
            KVs[r][d4 + 2] = v.z; KVs[r][d4 + 3] = v.w;
        }
        __syncthreads();

        // S = Q @ K^T  (8x4 fragment per thread)
        float s[8][4];
#pragma unroll
        for (int i = 0; i < 8; i++)
#pragma unroll
            for (int j = 0; j < 4; j++) s[i][j] = 0.f;

#pragma unroll 4
        for (int k = 0; k < 64; k++) {
            float a[8], bb[4];
#pragma unroll
            for (int i = 0; i < 8; i++) a[i] = Qs[r0 + i][k];
#pragma unroll
            for (int j = 0; j < 4; j++) bb[j] = KVs[n0 + j][k];
#pragma unroll
            for (int i = 0; i < 8; i++)
#pragma unroll
                for (int j = 0; j < 4; j++) s[i][j] += a[i] * bb[j];
        }

        // P = exp(S/8) with causal mask on the diagonal tile.
        const bool diag = (c == qt);
#pragma unroll
        for (int i = 0; i < 8; i++) {
            float p[4];
#pragma unroll
            for (int j = 0; j < 4; j++) {
                float e = __expf(s[i][j] * 0.125f);
                if (diag && (n0 + j) > (r0 + i)) e = 0.f;
                p[j] = e;
                rpart[i] += e;
                Ps[r0 + i][n0 + j] = e;
            }
            if (attn) {
                float4 pv; pv.x = p[0]; pv.y = p[1]; pv.z = p[2]; pv.w = p[3];
                *reinterpret_cast<float4*>(
                    attn + attnRow0 + (size_t)(r0 + i) * SEQ + kbase + n0) = pv;
            }
        }
        __syncthreads();   // done reading K, Ps fully written

        // Load V chunk [64 k][64 d]
#pragma unroll
        for (int it = 0; it < 8; it++) {
            int idx = tid + it * 128;
            int r  = idx >> 4;
            int d4 = (idx & 15) * 4;
            float4 v = *reinterpret_cast<const float4*>(
                Vp + qkvBase + (size_t)(kbase + r) * D_MODEL + d4);
            KVs[r][d4 + 0] = v.x; KVs[r][d4 + 1] = v.y;
            KVs[r][d4 + 2] = v.z; KVs[r][d4 + 3] = v.w;
        }
        __syncthreads();

        // ctx += P @ V
#pragma unroll 4
        for (int k = 0; k < 64; k++) {
            float a[8], bb[4];
#pragma unroll
            for (int i = 0; i < 8; i++) a[i] = Ps[r0 + i][k];
#pragma unroll
            for (int j = 0; j < 4; j++) bb[j] = KVs[k][n0 + j];
#pragma unroll
            for (int i = 0; i < 8; i++)
#pragma unroll
                for (int j = 0; j < 4; j++) ctxa[i][j] += a[i] * bb[j];
        }
        __syncthreads();   // before KVs/Ps reuse next chunk
    }

    // Reduce row sums across the 16 thread-columns (reuse Ps)
#pragma unroll
    for (int i = 0; i < 8; i++) Ps[r0 + i][tx] = rpart[i];
    __syncthreads();
    if (tid < 64) {
        float sm = 0.f;
#pragma unroll
        for (int x = 0; x < 16; x++) sm += Ps[tid][x];
        invs[tid] = 1.0f / sm;
    }
    __syncthreads();

    // Write normalized ctx: ctx[b, q, h*64 + d]
#pragma unroll
    for (int i = 0; i < 8; i++) {
        float inv = invs[r0 + i];
        float4 v;
        v.x = ctxa[i][0] * inv; v.y = ctxa[i][1] * inv;
        v.z = ctxa[i][2] * inv; v.w = ctxa[i][3] * inv;
        *reinterpret_cast<float4*>(
            ctx + qkvBase + (size_t)(qbase + r0 + i) * D_MODEL + n0) = v;
    }

    // Epilogue: rescale this block's attn rows; zero the masked region.
    if (attn) {
        for (int c = 0; c < SEQ / 64; c++) {
            const int kbase = c * 64;
            if (c <= qt) {
#pragma unroll
                for (int it = 0; it < 8; it++) {
                    int idx = tid + it * 128;
                    int r  = idx >> 4;
                    int d4 = (idx & 15) * 4;
                    float inv = invs[r];
                    float4* p = reinterpret_cast<float4*>(
                        attn + attnRow0 + (size_t)r * SEQ + kbase + d4);
                    float4 v = *p;
                    v.x *= inv; v.y *= inv; v.z *= inv; v.w *= inv;
                    *p = v;
                }
            } else {
                const float4 z = {0.f, 0.f, 0.f, 0.f};
#pragma unroll
                for (int it = 0; it < 8; it++) {
                    int idx = tid + it * 128;
                    int r  = idx >> 4;
                    int d4 = (idx & 15) * 4;
                    *reinterpret_cast<float4*>(
                        attn + attnRow0 + (size_t)r * SEQ + kbase + d4) = z;
                }
            }
        }
    }
}

// ---------------------------------------------------------------------------
extern "C" void kernel_launch(void* const* d_in, const int* in_sizes, int n_in,
                              void* d_out, int out_size)
{
    const float* q  = (const float*)d_in[0];
    const float* k  = (const float*)d_in[1];
    const float* v  = (const float*)d_in[2];
    // d_in[3] is the mask — causal structure applied analytically.
    const float* wq = (const float*)d_in[4];
    const float* bq = (const float*)d_in[5];
    const float* wk = (const float*)d_in[6];
    const float* bk = (const float*)d_in[7];
    const float* wv = (const float*)d_in[8];
    const float* bv = (const float*)d_in[9];
    const float* wo = (const float*)d_in[10];
    const float* bo = (const float*)d_in[11];

    float* out = (float*)d_out;
    float* attn = nullptr;
    if ((long long)out_size >= OUT_ELEMS + ATTN_ELEMS) {
        attn = out + OUT_ELEMS;
    }

    float *Qs, *Ks, *Vs, *Cs;
    cudaGetSymbolAddress((void**)&Qs, g_Q);
    cudaGetSymbolAddress((void**)&Ks, g_K);
    cudaGetSymbolAddress((void**)&Vs, g_V);
    cudaGetSymbolAddress((void**)&Cs, g_ctx);

    dim3 ggrid(D_MODEL / 128, MTOT / 128);   // (8, 32)
    gemm_bias_kernel<<<ggrid, 256>>>(q, wq, bq, Qs, MTOT, D_MODEL, D_MODEL);
    gemm_bias_kernel<<<ggrid, 256>>>(k, wk, bk, Ks, MTOT, D_MODEL, D_MODEL);
    gemm_bias_kernel<<<ggrid, 256>>>(v, wv, bv, Vs, MTOT, D_MODEL, D_MODEL);

    attn_pass1<<<dim3(SEQ / 64, BATCH * NUM_HEADS), 128>>>(Qs, Ks, Vs, attn, Cs);

    gemm_bias_kernel<<<ggrid, 256>>>(Cs, wo, bo, out, MTOT, D_MODEL, D_MODEL);
}

// round 13
// speedup vs baseline: 1.5492x; 1.4820x over previous
#include <cuda_runtime.h>
#include <cuda_bf16.h>
#include <cstdint>

#define D_MODEL 1024
#define NUM_HEADS 16
#define DEPTH 64
#define BATCH 2
#define SEQ 2048
#define MTOT (BATCH * SEQ)            // 4096 rows
#define OUT_ELEMS ((long long)BATCH * SEQ * D_MODEL)          // 4,194,304
#define ATTN_ELEMS ((long long)BATCH * NUM_HEADS * SEQ * SEQ) // 134,217,728

// Scratch (no allocations allowed)
__device__ float g_Q[MTOT * D_MODEL];
__device__ float g_K[MTOT * D_MODEL];
__device__ float g_V[MTOT * D_MODEL];
__device__ float g_ctx[MTOT * D_MODEL];
__device__ __nv_bfloat16 g_Ahi[MTOT * D_MODEL];
__device__ __nv_bfloat16 g_Alo[MTOT * D_MODEL];
__device__ __nv_bfloat16 g_Whi[D_MODEL * D_MODEL];
__device__ __nv_bfloat16 g_Wlo[D_MODEL * D_MODEL];

// ===========================================================================
// Generic-PTX helpers (sm_80+: legal under the harness's compute_103 pass)
// ===========================================================================
__device__ __forceinline__ uint32_t smem_to_u32(const void* p) {
    uint32_t a;
    asm("{ .reg .u64 t; cvta.to.shared.u64 t, %1; cvt.u32.u64 %0, t; }"
        : "=r"(a) : "l"(p));
    return a;
}
__device__ __forceinline__ void cp16(uint32_t s, const void* g) {
    asm volatile("cp.async.cg.shared.global [%0], [%1], 16;"
                 :: "r"(s), "l"(g) : "memory");
}
__device__ __forceinline__ void cp_commit() {
    asm volatile("cp.async.commit_group;" ::: "memory");
}
__device__ __forceinline__ void cp_wait_all() {
    asm volatile("cp.async.wait_group 0;" ::: "memory");
}
__device__ __forceinline__ void ldsm_x4(uint32_t* r, uint32_t addr) {
    asm volatile("ldmatrix.sync.aligned.m8n8.x4.shared.b16 {%0,%1,%2,%3}, [%4];"
                 : "=r"(r[0]), "=r"(r[1]), "=r"(r[2]), "=r"(r[3]) : "r"(addr));
}
__device__ __forceinline__ void mma_bf16(float* c, const uint32_t* a,
                                         uint32_t b0, uint32_t b1) {
    asm volatile(
        "mma.sync.aligned.m16n8k16.row.col.f32.bf16.bf16.f32 "
        "{%0,%1,%2,%3}, {%4,%5,%6,%7}, {%8,%9}, {%0,%1,%2,%3};"
        : "+f"(c[0]), "+f"(c[1]), "+f"(c[2]), "+f"(c[3])
        : "r"(a[0]), "r"(a[1]), "r"(a[2]), "r"(a[3]), "r"(b0), "r"(b1));
}

// ===========================================================================
// fp32 -> bf16 hi/lo split (vectorized)
// ===========================================================================
__global__ __launch_bounds__(256) void split_kernel(
    const float* __restrict__ X,
    __nv_bfloat16* __restrict__ Hi, __nv_bfloat16* __restrict__ Lo)
{
    int i = blockIdx.x * 256 + threadIdx.x;
    float4 v = reinterpret_cast<const float4*>(X)[i];
    __nv_bfloat16 h0 = __float2bfloat16(v.x);
    __nv_bfloat16 h1 = __float2bfloat16(v.y);
    __nv_bfloat16 h2 = __float2bfloat16(v.z);
    __nv_bfloat16 h3 = __float2bfloat16(v.w);
    __nv_bfloat16 l0 = __float2bfloat16(v.x - __bfloat162float(h0));
    __nv_bfloat16 l1 = __float2bfloat16(v.y - __bfloat162float(h1));
    __nv_bfloat16 l2 = __float2bfloat16(v.z - __bfloat162float(h2));
    __nv_bfloat16 l3 = __float2bfloat16(v.w - __bfloat162float(h3));
    __nv_bfloat162* H2 = reinterpret_cast<__nv_bfloat162*>(Hi);
    __nv_bfloat162* L2 = reinterpret_cast<__nv_bfloat162*>(Lo);
    H2[2 * i + 0] = __halves2bfloat162(h0, h1);
    H2[2 * i + 1] = __halves2bfloat162(h2, h3);
    L2[2 * i + 0] = __halves2bfloat162(l0, l1);
    L2[2 * i + 1] = __halves2bfloat162(l2, l3);
}

// W[K][N] fp32 -> T[N][K] bf16 hi/lo (transpose + split)
__global__ __launch_bounds__(256) void transpose_split_kernel(
    const float* __restrict__ W,
    __nv_bfloat16* __restrict__ Thi, __nv_bfloat16* __restrict__ Tlo)
{
    __shared__ float tile[32][33];
    int tx = threadIdx.x, ty = threadIdx.y;
    int n0 = blockIdx.x * 32, k0 = blockIdx.y * 32;
#pragma unroll
    for (int i = 0; i < 32; i += 8)
        tile[ty + i][tx] = W[(size_t)(k0 + ty + i) * D_MODEL + n0 + tx];
    __syncthreads();
#pragma unroll
    for (int i = 0; i < 32; i += 8) {
        float v = tile[tx][ty + i];
        __nv_bfloat16 h = __float2bfloat16(v);
        __nv_bfloat16 l = __float2bfloat16(v - __bfloat162float(h));
        size_t o = (size_t)(n0 + ty + i) * D_MODEL + k0 + tx;
        Thi[o] = h; Tlo[o] = l;
    }
}

// ===========================================================================
// HMMA bf16-split GEMM: C[M,N] = A[M,K] @ Bt[N,K]^T + bias
// 128x128 tile, BK=64, 8 warps (2x4), warp tile 64x32, double-buffered
// cp.async, SW128-xor swizzle for conflict-free ldmatrix.
// ===========================================================================
#define GBM 128
#define GBN 128
#define GBK 64
#define TILE16K 16384
#define STAGEB (4 * TILE16K)          // Ahi,Alo,Bhi,Blo  = 64 KB
#define GEMM_SMEM (2 * STAGEB)        // 128 KB

__global__ __launch_bounds__(256, 1)
void gemm_hmma(const __nv_bfloat16* __restrict__ Ahi, const __nv_bfloat16* __restrict__ Alo,
               const __nv_bfloat16* __restrict__ Bhi, const __nv_bfloat16* __restrict__ Blo,
               const float* __restrict__ bias, float* __restrict__ C)
{
    extern __shared__ char smem[];
    const uint32_t sb = smem_to_u32(smem);
    const int tid  = threadIdx.x;
    const int lane = tid & 31;
    const int wid  = tid >> 5;
    const int wm   = wid >> 2;          // 0..1 (64 rows)
    const int wn   = wid & 3;           // 0..3 (32 cols)
    const int bm   = blockIdx.y * GBM;
    const int bn   = blockIdx.x * GBN;

    const char* pAh = reinterpret_cast<const char*>(Ahi);
    const char* pAl = reinterpret_cast<const char*>(Alo);
    const char* pBh = reinterpret_cast<const char*>(Bhi);
    const char* pBl = reinterpret_cast<const char*>(Blo);

    // per-thread load geometry (same for all 4 sub-tiles)
    // idx = it*256+tid -> r = idx>>3 (0..127), ch = idx&7 (16B chunk)
    // smem offset = r*128 + ((ch ^ (r&7))<<4)

    // fragment geometry
    const int frA  = wm * 64 + (lane & 15);      // + mt*16
    const int frB  = wn * 32 + (lane & 15);      // + bt*16
    const int fch  = lane >> 4;                  // + ks*2
    const int a7   = frA & 7;
    const int b7   = frB & 7;

    float acc[4][4][4];
#pragma unroll
    for (int mt = 0; mt < 4; mt++)
#pragma unroll
        for (int nt = 0; nt < 4; nt++)
#pragma unroll
            for (int j = 0; j < 4; j++) acc[mt][nt][j] = 0.f;

    // ---- prologue: load chunk 0 into stage 0 ----
    {
        const int k0 = 0;
#pragma unroll
        for (int it = 0; it < 4; it++) {
            int idx = it * 256 + tid;
            int r = idx >> 3, ch = idx & 7;
            uint32_t soff = r * 128 + ((ch ^ (r & 7)) << 4);
            size_t goA = (((size_t)(bm + r) << 10) + k0 + ch * 8) * 2;
            size_t goB = (((size_t)(bn + r) << 10) + k0 + ch * 8) * 2;
            cp16(sb + soff,                pAh + goA);
            cp16(sb + TILE16K + soff,      pAl + goA);
            cp16(sb + 2 * TILE16K + soff,  pBh + goB);
            cp16(sb + 3 * TILE16K + soff,  pBl + goB);
        }
        cp_commit();
    }

    for (int c = 0; c < D_MODEL / GBK; c++) {       // 16 chunks
        cp_wait_all();
        __syncthreads();

        if (c + 1 < D_MODEL / GBK) {
            const int k0 = (c + 1) * GBK;
            const uint32_t sdst = sb + ((c + 1) & 1) * STAGEB;
#pragma unroll
            for (int it = 0; it < 4; it++) {
                int idx = it * 256 + tid;
                int r = idx >> 3, ch = idx & 7;
                uint32_t soff = r * 128 + ((ch ^ (r & 7)) << 4);
                size_t goA = (((size_t)(bm + r) << 10) + k0 + ch * 8) * 2;
                size_t goB = (((size_t)(bn + r) << 10) + k0 + ch * 8) * 2;
                cp16(sdst + soff,               pAh + goA);
                cp16(sdst + TILE16K + soff,     pAl + goA);
                cp16(sdst + 2 * TILE16K + soff, pBh + goB);
                cp16(sdst + 3 * TILE16K + soff, pBl + goB);
            }
        }
        cp_commit();

        const uint32_t sA = sb + (c & 1) * STAGEB;
#pragma unroll
        for (int ks = 0; ks < 4; ks++) {            // 4 k16-steps per chunk
            uint32_t ah[4][4], al[4][4], bh[2][4], bl[2][4];
#pragma unroll
            for (int mt = 0; mt < 4; mt++) {
                uint32_t addr = sA + (uint32_t)(frA + mt * 16) * 128 +
                                ((uint32_t)((ks * 2 + fch) ^ a7) << 4);
                ldsm_x4(ah[mt], addr);
                ldsm_x4(al[mt], addr + TILE16K);
            }
#pragma unroll
            for (int bt = 0; bt < 2; bt++) {
                uint32_t addr = sA + 2 * TILE16K + (uint32_t)(frB + bt * 16) * 128 +
                                ((uint32_t)((ks * 2 + fch) ^ b7) << 4);
                ldsm_x4(bh[bt], addr);
                ldsm_x4(bl[bt], addr + TILE16K);
            }
#pragma unroll
            for (int mt = 0; mt < 4; mt++) {
#pragma unroll
                for (int nt = 0; nt < 4; nt++) {
                    const int bt = nt >> 1, wq = nt & 1;
                    mma_bf16(acc[mt][nt], ah[mt], bh[bt][wq], bh[bt][wq + 2]);
                    mma_bf16(acc[mt][nt], ah[mt], bl[bt][wq], bl[bt][wq + 2]);
                    mma_bf16(acc[mt][nt], al[mt], bh[bt][wq], bh[bt][wq + 2]);
                }
            }
        }
        __syncthreads();
    }

    // ---- epilogue: bias + store ----
    const int row0 = bm + wm * 64 + (lane >> 2);
    const int col0 = bn + wn * 32 + (lane & 3) * 2;
#pragma unroll
    for (int mt = 0; mt < 4; mt++) {
#pragma unroll
        for (int nt = 0; nt < 4; nt++) {
            const int r = row0 + mt * 16;
            const int cc = col0 + nt * 8;
            float2 bv = *reinterpret_cast<const float2*>(bias + cc);
            float2 o0 = {acc[mt][nt][0] + bv.x, acc[mt][nt][1] + bv.y};
            float2 o1 = {acc[mt][nt][2] + bv.x, acc[mt][nt][3] + bv.y};
            *reinterpret_cast<float2*>(C + (size_t)r * D_MODEL + cc) = o0;
            *reinterpret_cast<float2*>(C + (size_t)(r + 8) * D_MODEL + cc) = o1;
        }
    }
}

// ---------------------------------------------------------------------------
// Register-tiled causal attention (unchanged from R11 best).
// ---------------------------------------------------------------------------
__global__ __launch_bounds__(128, 4) void attn_pass1(
    const float* __restrict__ Qp, const float* __restrict__ Kp,
    const float* __restrict__ Vp, float* __restrict__ attn,
    float* __restrict__ ctx)
{
    __shared__ float Qs[64][65];
    __shared__ float KVs[64][65];
    __shared__ float Ps[64][65];
    __shared__ float invs[64];

    const int tid   = threadIdx.x;
    const int qt    = (int)gridDim.x - 1 - (int)blockIdx.x;
    const int h     = blockIdx.y & (NUM_HEADS - 1);
    const int b     = blockIdx.y >> 4;
    const int qbase = qt * 64;

    const int tx = tid & 15;
    const int ty = tid >> 4;
    const int r0 = ty * 8;
    const int n0 = tx * 4;

    const size_t qkvBase  = (size_t)b * SEQ * D_MODEL + (size_t)h * DEPTH;
    const size_t attnRow0 = (((size_t)b * NUM_HEADS + h) * SEQ + qbase) * SEQ;

#pragma unroll
    for (int it = 0; it < 8; it++) {
        int idx = tid + it * 128;
        int r  = idx >> 4;
        int d4 = (idx & 15) * 4;
        float4 v = *reinterpret_cast<const float4*>(
            Qp + qkvBase + (size_t)(qbase + r) * D_MODEL + d4);
        Qs[r][d4 + 0] = v.x; Qs[r][d4 + 1] = v.y;
        Qs[r][d4 + 2] = v.z; Qs[r][d4 + 3] = v.w;
    }

    float ctxa[8][4];
    float rpart[8];
#pragma unroll
    for (int i = 0; i < 8; i++) {
        rpart[i] = 0.f;
#pragma unroll
        for (int j = 0; j < 4; j++) ctxa[i][j] = 0.f;
    }
    __syncthreads();

    for (int c = 0; c <= qt; c++) {
        const int kbase = c * 64;
#pragma unroll
        for (int it = 0; it < 8; it++) {
            int idx = tid + it * 128;
            int r  = idx >> 4;
            int d4 = (idx & 15) * 4;
            float4 v = *reinterpret_cast<const float4*>(
                Kp + qkvBase + (size_t)(kbase + r) * D_MODEL + d4);
            KVs[r][d4 + 0] = v.x; KVs[r][d4 + 1] = v.y;
            KVs[r][d4 + 2] = v.z; KVs[r][d4 + 3] = v.w;
        }
        __syncthreads();

        float s[8][4];
#pragma unroll
        for (int i = 0; i < 8; i++)
#pragma unroll
            for (int j = 0; j < 4; j++) s[i][j] = 0.f;

#pragma unroll 4
        for (int k = 0; k < 64; k++) {
            float a[8], bb[4];
#pragma unroll
            for (int i = 0; i < 8; i++) a[i] = Qs[r0 + i][k];
#pragma unroll
            for (int j = 0; j < 4; j++) bb[j] = KVs[n0 + j][k];
#pragma unroll
            for (int i = 0; i < 8; i++)
#pragma unroll
                for (int j = 0; j < 4; j++) s[i][j] += a[i] * bb[j];
        }

        const bool diag = (c == qt);
#pragma unroll
        for (int i = 0; i < 8; i++) {
            float p[4];
#pragma unroll
            for (int j = 0; j < 4; j++) {
                float e = __expf(s[i][j] * 0.125f);
                if (diag && (n0 + j) > (r0 + i)) e = 0.f;
                p[j] = e;
                rpart[i] += e;
                Ps[r0 + i][n0 + j] = e;
            }
            if (attn) {
                float4 pv; pv.x = p[0]; pv.y = p[1]; pv.z = p[2]; pv.w = p[3];
                *reinterpret_cast<float4*>(
                    attn + attnRow0 + (size_t)(r0 + i) * SEQ + kbase + n0) = pv;
            }
        }
        __syncthreads();

#pragma unroll
        for (int it = 0; it < 8; it++) {
            int idx = tid + it * 128;
            int r  = idx >> 4;
            int d4 = (idx & 15) * 4;
            float4 v = *reinterpret_cast<const float4*>(
                Vp + qkvBase + (size_t)(kbase + r) * D_MODEL + d4);
            KVs[r][d4 + 0] = v.x; KVs[r][d4 + 1] = v.y;
            KVs[r][d4 + 2] = v.z; KVs[r][d4 + 3] = v.w;
        }
        __syncthreads();

#pragma unroll 4
        for (int k = 0; k < 64; k++) {
            float a[8], bb[4];
#pragma unroll
            for (int i = 0; i < 8; i++) a[i] = Ps[r0 + i][k];
#pragma unroll
            for (int j = 0; j < 4; j++) bb[j] = KVs[k][n0 + j];
#pragma unroll
            for (int i = 0; i < 8; i++)
#pragma unroll
                for (int j = 0; j < 4; j++) ctxa[i][j] += a[i] * bb[j];
        }
        __syncthreads();
    }

#pragma unroll
    for (int i = 0; i < 8; i++) Ps[r0 + i][tx] = rpart[i];
    __syncthreads();
    if (tid < 64) {
        float sm = 0.f;
#pragma unroll
        for (int x = 0; x < 16; x++) sm += Ps[tid][x];
        invs[tid] = 1.0f / sm;
    }
    __syncthreads();

#pragma unroll
    for (int i = 0; i < 8; i++) {
        float inv = invs[r0 + i];
        float4 v;
        v.x = ctxa[i][0] * inv; v.y = ctxa[i][1] * inv;
        v.z = ctxa[i][2] * inv; v.w = ctxa[i][3] * inv;
        *reinterpret_cast<float4*>(
            ctx + qkvBase + (size_t)(qbase + r0 + i) * D_MODEL + n0) = v;
    }

    if (attn) {
        for (int c = 0; c < SEQ / 64; c++) {
            const int kbase = c * 64;
            if (c <= qt) {
#pragma unroll
                for (int it = 0; it < 8; it++) {
                    int idx = tid + it * 128;
                    int r  = idx >> 4;
                    int d4 = (idx & 15) * 4;
                    float inv = invs[r];
                    float4* p = reinterpret_cast<float4*>(
                        attn + attnRow0 + (size_t)r * SEQ + kbase + d4);
                    float4 v = *p;
                    v.x *= inv; v.y *= inv; v.z *= inv; v.w *= inv;
                    *p = v;
                }
            } else {
                const float4 z = {0.f, 0.f, 0.f, 0.f};
#pragma unroll
                for (int it = 0; it < 8; it++) {
                    int idx = tid + it * 128;
                    int r  = idx >> 4;
                    int d4 = (idx & 15) * 4;
                    *reinterpret_cast<float4*>(
                        attn + attnRow0 + (size_t)r * SEQ + kbase + d4) = z;
                }
            }
        }
    }
}

// ---------------------------------------------------------------------------
extern "C" void kernel_launch(void* const* d_in, const int* in_sizes, int n_in,
                              void* d_out, int out_size)
{
    const float* q  = (const float*)d_in[0];
    const float* k  = (const float*)d_in[1];
    const float* v  = (const float*)d_in[2];
    const float* wq = (const float*)d_in[4];
    const float* bq = (const float*)d_in[5];
    const float* wk = (const float*)d_in[6];
    const float* bk = (const float*)d_in[7];
    const float* wv = (const float*)d_in[8];
    const float* bv = (const float*)d_in[9];
    const float* wo = (const float*)d_in[10];
    const float* bo = (const float*)d_in[11];

    float* out = (float*)d_out;
    float* attn = nullptr;
    if ((long long)out_size >= OUT_ELEMS + ATTN_ELEMS) attn = out + OUT_ELEMS;

    float *Qs, *Ks, *Vs, *Cs;
    __nv_bfloat16 *Ahi, *Alo, *Whi, *Wlo;
    cudaGetSymbolAddress((void**)&Qs, g_Q);
    cudaGetSymbolAddress((void**)&Ks, g_K);
    cudaGetSymbolAddress((void**)&Vs, g_V);
    cudaGetSymbolAddress((void**)&Cs, g_ctx);
    cudaGetSymbolAddress((void**)&Ahi, g_Ahi);
    cudaGetSymbolAddress((void**)&Alo, g_Alo);
    cudaGetSymbolAddress((void**)&Whi, g_Whi);
    cudaGetSymbolAddress((void**)&Wlo, g_Wlo);

    cudaFuncSetAttribute(gemm_hmma, cudaFuncAttributeMaxDynamicSharedMemorySize,
                         GEMM_SMEM);

    const int splitBlocks = (MTOT * D_MODEL / 4) / 256;   // 4096
    dim3 tgrid(D_MODEL / 32, D_MODEL / 32);               // (32,32)
    dim3 tblock(32, 8);
    dim3 ggrid(D_MODEL / GBN, MTOT / GBM);                // (8, 32)

    split_kernel<<<splitBlocks, 256>>>(q, Ahi, Alo);
    transpose_split_kernel<<<tgrid, tblock>>>(wq, Whi, Wlo);
    gemm_hmma<<<ggrid, 256, GEMM_SMEM>>>(Ahi, Alo, Whi, Wlo, bq, Qs);

    split_kernel<<<splitBlocks, 256>>>(k, Ahi, Alo);
    transpose_split_kernel<<<tgrid, tblock>>>(wk, Whi, Wlo);
    gemm_hmma<<<ggrid, 256, GEMM_SMEM>>>(Ahi, Alo, Whi, Wlo, bk, Ks);

    split_kernel<<<splitBlocks, 256>>>(v, Ahi, Alo);
    transpose_split_kernel<<<tgrid, tblock>>>(wv, Whi, Wlo);
    gemm_hmma<<<ggrid, 256, GEMM_SMEM>>>(Ahi, Alo, Whi, Wlo, bv, Vs);

    attn_pass1<<<dim3(SEQ / 64, BATCH * NUM_HEADS), 128>>>(Qs, Ks, Vs, attn, Cs);

    split_kernel<<<splitBlocks, 256>>>(Cs, Ahi, Alo);
    transpose_split_kernel<<<tgrid, tblock>>>(wo, Whi, Wlo);
    gemm_hmma<<<ggrid, 256, GEMM_SMEM>>>(Ahi, Alo, Whi, Wlo, bo, out);
}

// round 15
// speedup vs baseline: 2.0332x; 1.3124x over previous
#include <cuda_runtime.h>
#include <cuda_bf16.h>
#include <cstdint>

#define D_MODEL 1024
#define NUM_HEADS 16
#define DEPTH 64
#define BATCH 2
#define SEQ 2048
#define MTOT (BATCH * SEQ)            // 4096 rows
#define OUT_ELEMS ((long long)BATCH * SEQ * D_MODEL)          // 4,194,304
#define ATTN_ELEMS ((long long)BATCH * NUM_HEADS * SEQ * SEQ) // 134,217,728

// Scratch (no allocations allowed) — bf16 hi/lo pairs
__device__ __nv_bfloat16 g_Ahi[MTOT * D_MODEL];
__device__ __nv_bfloat16 g_Alo[MTOT * D_MODEL];
__device__ __nv_bfloat16 g_Whi[D_MODEL * D_MODEL];
__device__ __nv_bfloat16 g_Wlo[D_MODEL * D_MODEL];
__device__ __nv_bfloat16 g_Qhi[MTOT * D_MODEL];
__device__ __nv_bfloat16 g_Qlo[MTOT * D_MODEL];
__device__ __nv_bfloat16 g_Khi[MTOT * D_MODEL];
__device__ __nv_bfloat16 g_Klo[MTOT * D_MODEL];
__device__ __nv_bfloat16 g_Vhi[MTOT * D_MODEL];
__device__ __nv_bfloat16 g_Vlo[MTOT * D_MODEL];
__device__ __nv_bfloat16 g_Chi[MTOT * D_MODEL];
__device__ __nv_bfloat16 g_Clo[MTOT * D_MODEL];

// ===========================================================================
// Generic-PTX helpers (sm_80+: legal under the harness's compute_103 pass)
// ===========================================================================
__device__ __forceinline__ uint32_t smem_to_u32(const void* p) {
    uint32_t a;
    asm("{ .reg .u64 t; cvta.to.shared.u64 t, %1; cvt.u32.u64 %0, t; }"
        : "=r"(a) : "l"(p));
    return a;
}
__device__ __forceinline__ void cp16(uint32_t s, const void* g) {
    asm volatile("cp.async.cg.shared.global [%0], [%1], 16;"
                 :: "r"(s), "l"(g) : "memory");
}
__device__ __forceinline__ void cp_commit() {
    asm volatile("cp.async.commit_group;" ::: "memory");
}
__device__ __forceinline__ void cp_wait_all() {
    asm volatile("cp.async.wait_group 0;" ::: "memory");
}
__device__ __forceinline__ void ldsm_x4(uint32_t* r, uint32_t addr) {
    asm volatile("ldmatrix.sync.aligned.m8n8.x4.shared.b16 {%0,%1,%2,%3}, [%4];"
                 : "=r"(r[0]), "=r"(r[1]), "=r"(r[2]), "=r"(r[3]) : "r"(addr));
}
__device__ __forceinline__ void ldsm_x4_t(uint32_t* r, uint32_t addr) {
    asm volatile("ldmatrix.sync.aligned.m8n8.x4.trans.shared.b16 {%0,%1,%2,%3}, [%4];"
                 : "=r"(r[0]), "=r"(r[1]), "=r"(r[2]), "=r"(r[3]) : "r"(addr));
}
__device__ __forceinline__ void mma_bf16(float* c, const uint32_t* a,
                                         uint32_t b0, uint32_t b1) {
    asm volatile(
        "mma.sync.aligned.m16n8k16.row.col.f32.bf16.bf16.f32 "
        "{%0,%1,%2,%3}, {%4,%5,%6,%7}, {%8,%9}, {%0,%1,%2,%3};"
        : "+f"(c[0]), "+f"(c[1]), "+f"(c[2]), "+f"(c[3])
        : "r"(a[0]), "r"(a[1]), "r"(a[2]), "r"(a[3]), "r"(b0), "r"(b1));
}
__device__ __forceinline__ uint32_t packbf(float lo, float hi) {
    __nv_bfloat162 t = __halves2bfloat162(__float2bfloat16(lo), __float2bfloat16(hi));
    return *reinterpret_cast<uint32_t*>(&t);
}

// ===========================================================================
// fp32 -> bf16 hi/lo split (vectorized)
// ===========================================================================
__global__ __launch_bounds__(256) void split_kernel(
    const float* __restrict__ X,
    __nv_bfloat16* __restrict__ Hi, __nv_bfloat16* __restrict__ Lo)
{
    int i = blockIdx.x * 256 + threadIdx.x;
    float4 v = reinterpret_cast<const float4*>(X)[i];
    __nv_bfloat16 h0 = __float2bfloat16(v.x);
    __nv_bfloat16 h1 = __float2bfloat16(v.y);
    __nv_bfloat16 h2 = __float2bfloat16(v.z);
    __nv_bfloat16 h3 = __float2bfloat16(v.w);
    __nv_bfloat16 l0 = __float2bfloat16(v.x - __bfloat162float(h0));
    __nv_bfloat16 l1 = __float2bfloat16(v.y - __bfloat162float(h1));
    __nv_bfloat16 l2 = __float2bfloat16(v.z - __bfloat162float(h2));
    __nv_bfloat16 l3 = __float2bfloat16(v.w - __bfloat162float(h3));
    __nv_bfloat162* H2 = reinterpret_cast<__nv_bfloat162*>(Hi);
    __nv_bfloat162* L2 = reinterpret_cast<__nv_bfloat162*>(Lo);
    H2[2 * i + 0] = __halves2bfloat162(h0, h1);
    H2[2 * i + 1] = __halves2bfloat162(h2, h3);
    L2[2 * i + 0] = __halves2bfloat162(l0, l1);
    L2[2 * i + 1] = __halves2bfloat162(l2, l3);
}

// W[K][N] fp32 -> T[N][K] bf16 hi/lo (transpose + split)
__global__ __launch_bounds__(256) void transpose_split_kernel(
    const float* __restrict__ W,
    __nv_bfloat16* __restrict__ Thi, __nv_bfloat16* __restrict__ Tlo)
{
    __shared__ float tile[32][33];
    int tx = threadIdx.x, ty = threadIdx.y;
    int n0 = blockIdx.x * 32, k0 = blockIdx.y * 32;
#pragma unroll
    for (int i = 0; i < 32; i += 8)
        tile[ty + i][tx] = W[(size_t)(k0 + ty + i) * D_MODEL + n0 + tx];
    __syncthreads();
#pragma unroll
    for (int i = 0; i < 32; i += 8) {
        float v = tile[tx][ty + i];
        __nv_bfloat16 h = __float2bfloat16(v);
        __nv_bfloat16 l = __float2bfloat16(v - __bfloat162float(h));
        size_t o = (size_t)(n0 + ty + i) * D_MODEL + k0 + tx;
        Thi[o] = h; Tlo[o] = l;
    }
}

// ===========================================================================
// HMMA bf16-split GEMM: C[M,N] = A[M,K] @ Bt[N,K]^T + bias
// Output either fp32 (Cf) or bf16 hi/lo pair (Chi/Clo).
// ===========================================================================
#define GBM 128
#define GBN 128
#define GBK 64
#define TILE16K 16384
#define STAGEB (4 * TILE16K)          // Ahi,Alo,Bhi,Blo  = 64 KB
#define GEMM_SMEM (2 * STAGEB)        // 128 KB

__global__ __launch_bounds__(256, 1)
void gemm_hmma(const __nv_bfloat16* __restrict__ Ahi, const __nv_bfloat16* __restrict__ Alo,
               const __nv_bfloat16* __restrict__ Bhi, const __nv_bfloat16* __restrict__ Blo,
               const float* __restrict__ bias, float* __restrict__ Cf,
               __nv_bfloat16* __restrict__ Chi, __nv_bfloat16* __restrict__ Clo)
{
    extern __shared__ char smem[];
    const uint32_t sb = smem_to_u32(smem);
    const int tid  = threadIdx.x;
    const int lane = tid & 31;
    const int wid  = tid >> 5;
    const int wm   = wid >> 2;
    const int wn   = wid & 3;
    const int bm   = blockIdx.y * GBM;
    const int bn   = blockIdx.x * GBN;

    const char* pAh = reinterpret_cast<const char*>(Ahi);
    const char* pAl = reinterpret_cast<const char*>(Alo);
    const char* pBh = reinterpret_cast<const char*>(Bhi);
    const char* pBl = reinterpret_cast<const char*>(Blo);

    const int frA  = wm * 64 + (lane & 15);
    const int frB  = wn * 32 + (lane & 15);
    const int fch  = lane >> 4;
    const int a7   = frA & 7;
    const int b7   = frB & 7;

    float acc[4][4][4];
#pragma unroll
    for (int mt = 0; mt < 4; mt++)
#pragma unroll
        for (int nt = 0; nt < 4; nt++)
#pragma unroll
            for (int j = 0; j < 4; j++) acc[mt][nt][j] = 0.f;

    {
        const int k0 = 0;
#pragma unroll
        for (int it = 0; it < 4; it++) {
            int idx = it * 256 + tid;
            int r = idx >> 3, ch = idx & 7;
            uint32_t soff = r * 128 + ((ch ^ (r & 7)) << 4);
            size_t goA = (((size_t)(bm + r) << 10) + k0 + ch * 8) * 2;
            size_t goB = (((size_t)(bn + r) << 10) + k0 + ch * 8) * 2;
            cp16(sb + soff,                pAh + goA);
            cp16(sb + TILE16K + soff,      pAl + goA);
            cp16(sb + 2 * TILE16K + soff,  pBh + goB);
            cp16(sb + 3 * TILE16K + soff,  pBl + goB);
        }
        cp_commit();
    }

    for (int c = 0; c < D_MODEL / GBK; c++) {
        cp_wait_all();
        __syncthreads();

        if (c + 1 < D_MODEL / GBK) {
            const int k0 = (c + 1) * GBK;
            const uint32_t sdst = sb + ((c + 1) & 1) * STAGEB;
#pragma unroll
            for (int it = 0; it < 4; it++) {
                int idx = it * 256 + tid;
                int r = idx >> 3, ch = idx & 7;
                uint32_t soff = r * 128 + ((ch ^ (r & 7)) << 4);
                size_t goA = (((size_t)(bm + r) << 10) + k0 + ch * 8) * 2;
                size_t goB = (((size_t)(bn + r) << 10) + k0 + ch * 8) * 2;
                cp16(sdst + soff,               pAh + goA);
                cp16(sdst + TILE16K + soff,     pAl + goA);
                cp16(sdst + 2 * TILE16K + soff, pBh + goB);
                cp16(sdst + 3 * TILE16K + soff, pBl + goB);
            }
        }
        cp_commit();

        const uint32_t sA = sb + (c & 1) * STAGEB;
#pragma unroll
        for (int ks = 0; ks < 4; ks++) {
            uint32_t ah[4][4], al[4][4], bh[2][4], bl[2][4];
#pragma unroll
            for (int mt = 0; mt < 4; mt++) {
                uint32_t addr = sA + (uint32_t)(frA + mt * 16) * 128 +
                                ((uint32_t)((ks * 2 + fch) ^ a7) << 4);
                ldsm_x4(ah[mt], addr);
                ldsm_x4(al[mt], addr + TILE16K);
            }
#pragma unroll
            for (int bt = 0; bt < 2; bt++) {
                uint32_t addr = sA + 2 * TILE16K + (uint32_t)(frB + bt * 16) * 128 +
                                ((uint32_t)((ks * 2 + fch) ^ b7) << 4);
                ldsm_x4(bh[bt], addr);
                ldsm_x4(bl[bt], addr + TILE16K);
            }
#pragma unroll
            for (int mt = 0; mt < 4; mt++) {
#pragma unroll
                for (int nt = 0; nt < 4; nt++) {
                    const int bt = nt >> 1, wq = nt & 1;
                    mma_bf16(acc[mt][nt], ah[mt], bh[bt][wq], bh[bt][wq + 2]);
                    mma_bf16(acc[mt][nt], ah[mt], bl[bt][wq], bl[bt][wq + 2]);
                    mma_bf16(acc[mt][nt], al[mt], bh[bt][wq], bh[bt][wq + 2]);
                }
            }
        }
        __syncthreads();
    }

    const int row0 = bm + wm * 64 + (lane >> 2);
    const int col0 = bn + wn * 32 + (lane & 3) * 2;
#pragma unroll
    for (int mt = 0; mt < 4; mt++) {
#pragma unroll
        for (int nt = 0; nt < 4; nt++) {
            const int r = row0 + mt * 16;
            const int cc = col0 + nt * 8;
            float2 bv = *reinterpret_cast<const float2*>(bias + cc);
            float v0 = acc[mt][nt][0] + bv.x, v1 = acc[mt][nt][1] + bv.y;
            float v2 = acc[mt][nt][2] + bv.x, v3 = acc[mt][nt][3] + bv.y;
            if (Cf) {
                *reinterpret_cast<float2*>(Cf + (size_t)r * D_MODEL + cc) =
                    make_float2(v0, v1);
                *reinterpret_cast<float2*>(Cf + (size_t)(r + 8) * D_MODEL + cc) =
                    make_float2(v2, v3);
            } else {
                __nv_bfloat16 h0 = __float2bfloat16(v0), h1 = __float2bfloat16(v1);
                __nv_bfloat16 h2 = __float2bfloat16(v2), h3 = __float2bfloat16(v3);
                __nv_bfloat16 l0 = __float2bfloat16(v0 - __bfloat162float(h0));
                __nv_bfloat16 l1 = __float2bfloat16(v1 - __bfloat162float(h1));
                __nv_bfloat16 l2 = __float2bfloat16(v2 - __bfloat162float(h2));
                __nv_bfloat16 l3 = __float2bfloat16(v3 - __bfloat162float(h3));
                *reinterpret_cast<__nv_bfloat162*>(Chi + (size_t)r * D_MODEL + cc) =
                    __halves2bfloat162(h0, h1);
                *reinterpret_cast<__nv_bfloat162*>(Clo + (size_t)r * D_MODEL + cc) =
                    __halves2bfloat162(l0, l1);
                *reinterpret_cast<__nv_bfloat162*>(Chi + (size_t)(r + 8) * D_MODEL + cc) =
                    __halves2bfloat162(h2, h3);
                *reinterpret_cast<__nv_bfloat162*>(Clo + (size_t)(r + 8) * D_MODEL + cc) =
                    __halves2bfloat162(l2, l3);
            }
        }
    }
}

// ===========================================================================
// HMMA causal attention. Block = (b,h,64-row q-tile), 128 threads (4 warps).
// S = QK^T via 3-MMA bf16 split; exp in registers; P split hi/lo in regs;
// ctx = Phi@Vhi + Plo@Vhi + Phi@Vlo (3-MMA split, ~1e-5 accuracy).
// Unnormalized P written to attn, rescaled in epilogue. ctx -> bf16 hi/lo.
// ===========================================================================
#define ATT_STG 32768                 // Khi 8K + Klo 8K + Vhi 8K + Vlo 8K
#define ATT_SMEM (16384 + 2 * ATT_STG + 512)

__global__ __launch_bounds__(128)
void attn_hmma(const __nv_bfloat16* __restrict__ Qhi, const __nv_bfloat16* __restrict__ Qlo,
               const __nv_bfloat16* __restrict__ Khi, const __nv_bfloat16* __restrict__ Klo,
               const __nv_bfloat16* __restrict__ Vhi, const __nv_bfloat16* __restrict__ Vlo,
               float* __restrict__ attn,
               __nv_bfloat16* __restrict__ Chi, __nv_bfloat16* __restrict__ Clo)
{
    extern __shared__ char smem[];
    const uint32_t sb = smem_to_u32(smem);
    const uint32_t sQ = sb;                       // Qhi 8K, Qlo 8K
    float* sRow = reinterpret_cast<float*>(smem + 16384 + 2 * ATT_STG);
    float* sInv = sRow + 64;

    const int tid  = threadIdx.x;
    const int lane = tid & 31;
    const int w    = tid >> 5;
    const int qt   = (int)gridDim.x - 1 - (int)blockIdx.x;   // largest first
    const int bh   = blockIdx.y;
    const int h    = bh & (NUM_HEADS - 1);
    const int b    = bh >> 4;
    const int qbase = qt * 64;

    const char* pQh = reinterpret_cast<const char*>(Qhi);
    const char* pQl = reinterpret_cast<const char*>(Qlo);
    const char* pKh = reinterpret_cast<const char*>(Khi);
    const char* pKl = reinterpret_cast<const char*>(Klo);
    const char* pVh = reinterpret_cast<const char*>(Vhi);
    const char* pVl = reinterpret_cast<const char*>(Vlo);

    const size_t rowStrideB = D_MODEL * 2;        // bytes per gmem row
    const size_t headOffB   = (size_t)h * DEPTH * 2;
    const size_t qRow0B = ((size_t)(b * SEQ + qbase)) * rowStrideB + headOffB;
    const size_t kRow0B = ((size_t)(b * SEQ)) * rowStrideB + headOffB;

    // ---- prologue: Q tile + chunk 0 ----
#pragma unroll
    for (int it = 0; it < 4; it++) {
        int idx = it * 128 + tid;                 // 0..511
        int r = idx >> 3, ch = idx & 7;
        uint32_t soff = r * 128 + ((ch ^ (r & 7)) << 4);
        size_t go = qRow0B + (size_t)r * rowStrideB + ch * 16;
        cp16(sQ + soff,        pQh + go);
        cp16(sQ + 8192 + soff, pQl + go);
        size_t gk = kRow0B + (size_t)r * rowStrideB + ch * 16;   // chunk 0
        uint32_t st0 = sb + 16384;
        cp16(st0 + soff,         pKh + gk);
        cp16(st0 + 8192 + soff,  pKl + gk);
        cp16(st0 + 16384 + soff, pVh + gk);
        cp16(st0 + 24576 + soff, pVl + gk);
    }
    cp_commit();
    cp_wait_all();
    __syncthreads();

    // ---- Q fragments (kept in registers across all chunks) ----
    uint32_t QAh[4][4], QAl[4][4];
    {
        const int qr = w * 16 + (lane & 15);
        const int q7 = qr & 7;
#pragma unroll
        for (int ks = 0; ks < 4; ks++) {
            uint32_t addr = sQ + (uint32_t)qr * 128 +
                            ((uint32_t)((ks * 2 + (lane >> 4)) ^ q7) << 4);
            ldsm_x4(QAh[ks], addr);
            ldsm_x4(QAl[ks], addr + 8192);
        }
    }

    float CT[8][4];
#pragma unroll
    for (int nt = 0; nt < 8; nt++)
#pragma unroll
        for (int j = 0; j < 4; j++) CT[nt][j] = 0.f;

    float rs0 = 0.f, rs1 = 0.f;
    const int rl = (lane >> 2);                   // 0..7
    const int tileRowLo = w * 16 + rl;            // 0..63 within q tile
    const int tileRowHi = tileRowLo + 8;
    const int colq = 2 * (lane & 3);              // 0..6 within 8-wide tile

    for (int c = 0; c <= qt; c++) {
        const int sp = c & 1;
        const uint32_t stb = sb + 16384 + sp * ATT_STG;

        if (c < qt) {
            const uint32_t sdst = sb + 16384 + (sp ^ 1) * ATT_STG;
            const size_t kRowB = kRow0B + (size_t)(c + 1) * 64 * rowStrideB;
#pragma unroll
            for (int it = 0; it < 4; it++) {
                int idx = it * 128 + tid;
                int r = idx >> 3, ch = idx & 7;
                uint32_t soff = r * 128 + ((ch ^ (r & 7)) << 4);
                size_t gk = kRowB + (size_t)r * rowStrideB + ch * 16;
                cp16(sdst + soff,         pKh + gk);
                cp16(sdst + 8192 + soff,  pKl + gk);
                cp16(sdst + 16384 + soff, pVh + gk);
                cp16(sdst + 24576 + soff, pVl + gk);
            }
        }
        cp_commit();

        // ---- S = Q @ K^T (3-MMA split) ----
        float S[8][4];
#pragma unroll
        for (int nt = 0; nt < 8; nt++)
#pragma unroll
            for (int j = 0; j < 4; j++) S[nt][j] = 0.f;

#pragma unroll
        for (int ks = 0; ks < 4; ks++) {
            uint32_t kbh[4][4], kbl[4][4];
#pragma unroll
            for (int g = 0; g < 4; g++) {
                const int kr = g * 16 + (lane & 15);
                uint32_t addr = stb + (uint32_t)kr * 128 +
                                ((uint32_t)((ks * 2 + (lane >> 4)) ^ (kr & 7)) << 4);
                ldsm_x4(kbh[g], addr);
                ldsm_x4(kbl[g], addr + 8192);
            }
#pragma unroll
            for (int g = 0; g < 4; g++) {
#pragma unroll
                for (int sub = 0; sub < 2; sub++) {
                    const int nt = 2 * g + sub;
                    mma_bf16(S[nt], QAh[ks], kbh[g][sub], kbh[g][sub + 2]);
                    mma_bf16(S[nt], QAh[ks], kbl[g][sub], kbl[g][sub + 2]);
                    mma_bf16(S[nt], QAl[ks], kbh[g][sub], kbh[g][sub + 2]);
                }
            }
        }

        // ---- exp, causal mask, attn store, row sums ----
        const int kb = c * 64;
        const bool diag = (c == qt);
        const size_t aRowLo = ((size_t)bh * SEQ + qbase + tileRowLo) * SEQ + kb;
        const size_t aRowHi = aRowLo + (size_t)8 * SEQ;
#pragma unroll
        for (int nt = 0; nt < 8; nt++) {
            const int tcol = nt * 8 + colq;
            float p0 = __expf(S[nt][0] * 0.125f);
            float p1 = __expf(S[nt][1] * 0.125f);
            float p2 = __expf(S[nt][2] * 0.125f);
            float p3 = __expf(S[nt][3] * 0.125f);
            if (diag) {
                if (tcol     > tileRowLo) p0 = 0.f;
                if (tcol + 1 > tileRowLo) p1 = 0.f;
                if (tcol     > tileRowHi) p2 = 0.f;
                if (tcol + 1 > tileRowHi) p3 = 0.f;
            }
            rs0 += p0 + p1;
            rs1 += p2 + p3;
            S[nt][0] = p0; S[nt][1] = p1; S[nt][2] = p2; S[nt][3] = p3;
            if (attn) {
                *reinterpret_cast<float2*>(attn + aRowLo + tcol) = make_float2(p0, p1);
                *reinterpret_cast<float2*>(attn + aRowHi + tcol) = make_float2(p2, p3);
            }
        }

        // ---- split P hi/lo, ctx += Phi@Vhi + Plo@Vhi + Phi@Vlo ----
#pragma unroll
        for (int ks = 0; ks < 4; ks++) {
            uint32_t PAh[4], PAl[4];
#pragma unroll
            for (int half = 0; half < 2; half++) {
                const float* sv = S[2 * ks + half];
#pragma unroll
                for (int pr = 0; pr < 2; pr++) {
                    float x0 = sv[2 * pr], x1 = sv[2 * pr + 1];
                    __nv_bfloat16 hh0 = __float2bfloat16(x0);
                    __nv_bfloat16 hh1 = __float2bfloat16(x1);
                    float r0f = x0 - __bfloat162float(hh0);
                    float r1f = x1 - __bfloat162float(hh1);
                    __nv_bfloat162 th = __halves2bfloat162(hh0, hh1);
                    __nv_bfloat162 tl = __halves2bfloat162(
                        __float2bfloat16(r0f), __float2bfloat16(r1f));
                    PAh[2 * half + pr] = *reinterpret_cast<uint32_t*>(&th);
                    PAl[2 * half + pr] = *reinterpret_cast<uint32_t*>(&tl);
                }
            }
#pragma unroll
            for (int g = 0; g < 4; g++) {
                const int vr = ks * 16 + (lane & 15);
                uint32_t addr = stb + 16384 + (uint32_t)vr * 128 +
                                ((uint32_t)((2 * g + (lane >> 4)) ^ (vr & 7)) << 4);
                uint32_t vbh[4], vbl[4];
                ldsm_x4_t(vbh, addr);
                ldsm_x4_t(vbl, addr + 8192);
                mma_bf16(CT[2 * g],     PAh, vbh[0], vbh[1]);
                mma_bf16(CT[2 * g],     PAl, vbh[0], vbh[1]);
                mma_bf16(CT[2 * g],     PAh, vbl[0], vbl[1]);
                mma_bf16(CT[2 * g + 1], PAh, vbh[2], vbh[3]);
                mma_bf16(CT[2 * g + 1], PAl, vbh[2], vbh[3]);
                mma_bf16(CT[2 * g + 1], PAh, vbl[2], vbl[3]);
            }
        }

        if (c < qt) {
            cp_wait_all();
            __syncthreads();
        }
    }

    // ---- row sums -> reciprocals ----
    rs0 += __shfl_xor_sync(0xFFFFFFFFu, rs0, 1);
    rs0 += __shfl_xor_sync(0xFFFFFFFFu, rs0, 2);
    rs1 += __shfl_xor_sync(0xFFFFFFFFu, rs1, 1);
    rs1 += __shfl_xor_sync(0xFFFFFFFFu, rs1, 2);
    if ((lane & 3) == 0) {
        sRow[tileRowLo] = rs0;
        sRow[tileRowHi] = rs1;
    }
    __syncthreads();
    if (tid < 64) sInv[tid] = 1.0f / sRow[tid];
    __syncthreads();

    // ---- normalized ctx -> bf16 hi/lo ----
    {
        const float inv0 = sInv[tileRowLo];
        const float inv1 = sInv[tileRowHi];
        const size_t cRowLo = ((size_t)(b * SEQ + qbase + tileRowLo)) * D_MODEL + h * DEPTH;
        const size_t cRowHi = cRowLo + (size_t)8 * D_MODEL;
#pragma unroll
        for (int nt = 0; nt < 8; nt++) {
            const int d = nt * 8 + colq;
            float v0 = CT[nt][0] * inv0, v1 = CT[nt][1] * inv0;
            float v2 = CT[nt][2] * inv1, v3 = CT[nt][3] * inv1;
            __nv_bfloat16 h0 = __float2bfloat16(v0), h1 = __float2bfloat16(v1);
            __nv_bfloat16 h2 = __float2bfloat16(v2), h3 = __float2bfloat16(v3);
            __nv_bfloat16 l0 = __float2bfloat16(v0 - __bfloat162float(h0));
            __nv_bfloat16 l1 = __float2bfloat16(v1 - __bfloat162float(h1));
            __nv_bfloat16 l2 = __float2bfloat16(v2 - __bfloat162float(h2));
            __nv_bfloat16 l3 = __float2bfloat16(v3 - __bfloat162float(h3));
            *reinterpret_cast<__nv_bfloat162*>(Chi + cRowLo + d) = __halves2bfloat162(h0, h1);
            *reinterpret_cast<__nv_bfloat162*>(Clo + cRowLo + d) = __halves2bfloat162(l0, l1);
            *reinterpret_cast<__nv_bfloat162*>(Chi + cRowHi + d) = __halves2bfloat162(h2, h3);
            *reinterpret_cast<__nv_bfloat162*>(Clo + cRowHi + d) = __halves2bfloat162(l2, l3);
        }
    }

    // ---- epilogue: rescale attn rows; zero masked region ----
    if (attn) {
        const size_t attnRow0 = ((size_t)bh * SEQ + qbase) * SEQ;
        for (int cc = 0; cc < SEQ / 64; cc++) {
            const int kb = cc * 64;
            if (cc <= qt) {
#pragma unroll
                for (int it = 0; it < 8; it++) {
                    int idx = tid + it * 128;
                    int r  = idx >> 4;
                    int d4 = (idx & 15) * 4;
                    float inv = sInv[r];
                    float4* p = reinterpret_cast<float4*>(
                        attn + attnRow0 + (size_t)r * SEQ + kb + d4);
                    float4 v = *p;
                    v.x *= inv; v.y *= inv; v.z *= inv; v.w *= inv;
                    *p = v;
                }
            } else {
                const float4 z = {0.f, 0.f, 0.f, 0.f};
#pragma unroll
                for (int it = 0; it < 8; it++) {
                    int idx = tid + it * 128;
                    int r  = idx >> 4;
                    int d4 = (idx & 15) * 4;
                    *reinterpret_cast<float4*>(
                        attn + attnRow0 + (size_t)r * SEQ + kb + d4) = z;
                }
            }
        }
    }
}

// ---------------------------------------------------------------------------
extern "C" void kernel_launch(void* const* d_in, const int* in_sizes, int n_in,
                              void* d_out, int out_size)
{
    const float* q  = (const float*)d_in[0];
    const float* k  = (const float*)d_in[1];
    const float* v  = (const float*)d_in[2];
    const float* wq = (const float*)d_in[4];
    const float* bq = (const float*)d_in[5];
    const float* wk = (const float*)d_in[6];
    const float* bk = (const float*)d_in[7];
    const float* wv = (const float*)d_in[8];
    const float* bv = (const float*)d_in[9];
    const float* wo = (const float*)d_in[10];
    const float* bo = (const float*)d_in[11];

    float* out = (float*)d_out;
    float* attn = nullptr;
    if ((long long)out_size >= OUT_ELEMS + ATTN_ELEMS) attn = out + OUT_ELEMS;

    __nv_bfloat16 *Ahi, *Alo, *Whi, *Wlo, *Qhi, *Qlo, *Khi, *Klo, *Vhi, *Vlo, *Chi, *Clo;
    cudaGetSymbolAddress((void**)&Ahi, g_Ahi);
    cudaGetSymbolAddress((void**)&Alo, g_Alo);
    cudaGetSymbolAddress((void**)&Whi, g_Whi);
    cudaGetSymbolAddress((void**)&Wlo, g_Wlo);
    cudaGetSymbolAddress((void**)&Qhi, g_Qhi);
    cudaGetSymbolAddress((void**)&Qlo, g_Qlo);
    cudaGetSymbolAddress((void**)&Khi, g_Khi);
    cudaGetSymbolAddress((void**)&Klo, g_Klo);
    cudaGetSymbolAddress((void**)&Vhi, g_Vhi);
    cudaGetSymbolAddress((void**)&Vlo, g_Vlo);
    cudaGetSymbolAddress((void**)&Chi, g_Chi);
    cudaGetSymbolAddress((void**)&Clo, g_Clo);

    cudaFuncSetAttribute(gemm_hmma, cudaFuncAttributeMaxDynamicSharedMemorySize,
                         GEMM_SMEM);
    cudaFuncSetAttribute(attn_hmma, cudaFuncAttributeMaxDynamicSharedMemorySize,
                         ATT_SMEM);

    const int splitBlocks = (MTOT * D_MODEL / 4) / 256;   // 4096
    dim3 tgrid(D_MODEL / 32, D_MODEL / 32);               // (32,32)
    dim3 tblock(32, 8);
    dim3 ggrid(D_MODEL / GBN, MTOT / GBM);                // (8, 32)

    split_kernel<<<splitBlocks, 256>>>(q, Ahi, Alo);
    transpose_split_kernel<<<tgrid, tblock>>>(wq, Whi, Wlo);
    gemm_hmma<<<ggrid, 256, GEMM_SMEM>>>(Ahi, Alo, Whi, Wlo, bq, nullptr, Qhi, Qlo);

    split_kernel<<<splitBlocks, 256>>>(k, Ahi, Alo);
    transpose_split_kernel<<<tgrid, tblock>>>(wk, Whi, Wlo);
    gemm_hmma<<<ggrid, 256, GEMM_SMEM>>>(Ahi, Alo, Whi, Wlo, bk, nullptr, Khi, Klo);

    split_kernel<<<splitBlocks, 256>>>(v, Ahi, Alo);
    transpose_split_kernel<<<tgrid, tblock>>>(wv, Whi, Wlo);
    gemm_hmma<<<ggrid, 256, GEMM_SMEM>>>(Ahi, Alo, Whi, Wlo, bv, nullptr, Vhi, Vlo);

    attn_hmma<<<dim3(SEQ / 64, BATCH * NUM_HEADS), 128, ATT_SMEM>>>(
        Qhi, Qlo, Khi, Klo, Vhi, Vlo, attn, Chi, Clo);

    transpose_split_kernel<<<tgrid, tblock>>>(wo, Whi, Wlo);
    gemm_hmma<<<ggrid, 256, GEMM_SMEM>>>(Chi, Clo, Whi, Wlo, bo, out, nullptr, nullptr);
}

// round 16
// speedup vs baseline: 2.4745x; 1.2170x over previous
#include <cuda_runtime.h>
#include <cuda_bf16.h>
#include <cstdint>

#define D_MODEL 1024
#define NUM_HEADS 16
#define DEPTH 64
#define BATCH 2
#define SEQ 2048
#define MTOT (BATCH * SEQ)            // 4096 rows
#define OUT_ELEMS ((long long)BATCH * SEQ * D_MODEL)          // 4,194,304
#define ATTN_ELEMS ((long long)BATCH * NUM_HEADS * SEQ * SEQ) // 134,217,728

// Scratch (no allocations allowed) — bf16 hi/lo pairs
__device__ __nv_bfloat16 g_Ahi[MTOT * D_MODEL];
__device__ __nv_bfloat16 g_Alo[MTOT * D_MODEL];
__device__ __nv_bfloat16 g_Whi[D_MODEL * D_MODEL];
__device__ __nv_bfloat16 g_Wlo[D_MODEL * D_MODEL];
__device__ __nv_bfloat16 g_Qhi[MTOT * D_MODEL];
__device__ __nv_bfloat16 g_Qlo[MTOT * D_MODEL];
__device__ __nv_bfloat16 g_Khi[MTOT * D_MODEL];
__device__ __nv_bfloat16 g_Klo[MTOT * D_MODEL];
__device__ __nv_bfloat16 g_Vhi[MTOT * D_MODEL];
__device__ __nv_bfloat16 g_Vlo[MTOT * D_MODEL];
__device__ __nv_bfloat16 g_Chi[MTOT * D_MODEL];
__device__ __nv_bfloat16 g_Clo[MTOT * D_MODEL];
__device__ float g_inv[BATCH * NUM_HEADS * SEQ];

// ===========================================================================
// Generic-PTX helpers (sm_80+: legal under the harness's compute_103 pass)
// ===========================================================================
__device__ __forceinline__ uint32_t smem_to_u32(const void* p) {
    uint32_t a;
    asm("{ .reg .u64 t; cvta.to.shared.u64 t, %1; cvt.u32.u64 %0, t; }"
        : "=r"(a) : "l"(p));
    return a;
}
__device__ __forceinline__ void cp16(uint32_t s, const void* g) {
    asm volatile("cp.async.cg.shared.global [%0], [%1], 16;"
                 :: "r"(s), "l"(g) : "memory");
}
__device__ __forceinline__ void cp_commit() {
    asm volatile("cp.async.commit_group;" ::: "memory");
}
__device__ __forceinline__ void cp_wait_all() {
    asm volatile("cp.async.wait_group 0;" ::: "memory");
}
__device__ __forceinline__ void ldsm_x4(uint32_t* r, uint32_t addr) {
    asm volatile("ldmatrix.sync.aligned.m8n8.x4.shared.b16 {%0,%1,%2,%3}, [%4];"
                 : "=r"(r[0]), "=r"(r[1]), "=r"(r[2]), "=r"(r[3]) : "r"(addr));
}
__device__ __forceinline__ void ldsm_x4_t(uint32_t* r, uint32_t addr) {
    asm volatile("ldmatrix.sync.aligned.m8n8.x4.trans.shared.b16 {%0,%1,%2,%3}, [%4];"
                 : "=r"(r[0]), "=r"(r[1]), "=r"(r[2]), "=r"(r[3]) : "r"(addr));
}
__device__ __forceinline__ void mma_bf16(float* c, const uint32_t* a,
                                         uint32_t b0, uint32_t b1) {
    asm volatile(
        "mma.sync.aligned.m16n8k16.row.col.f32.bf16.bf16.f32 "
        "{%0,%1,%2,%3}, {%4,%5,%6,%7}, {%8,%9}, {%0,%1,%2,%3};"
        : "+f"(c[0]), "+f"(c[1]), "+f"(c[2]), "+f"(c[3])
        : "r"(a[0]), "r"(a[1]), "r"(a[2]), "r"(a[3]), "r"(b0), "r"(b1));
}

// ===========================================================================
// fp32 -> bf16 hi/lo split (vectorized)
// ===========================================================================
__global__ __launch_bounds__(256) void split_kernel(
    const float* __restrict__ X,
    __nv_bfloat16* __restrict__ Hi, __nv_bfloat16* __restrict__ Lo)
{
    int i = blockIdx.x * 256 + threadIdx.x;
    float4 v = reinterpret_cast<const float4*>(X)[i];
    __nv_bfloat16 h0 = __float2bfloat16(v.x);
    __nv_bfloat16 h1 = __float2bfloat16(v.y);
    __nv_bfloat16 h2 = __float2bfloat16(v.z);
    __nv_bfloat16 h3 = __float2bfloat16(v.w);
    __nv_bfloat16 l0 = __float2bfloat16(v.x - __bfloat162float(h0));
    __nv_bfloat16 l1 = __float2bfloat16(v.y - __bfloat162float(h1));
    __nv_bfloat16 l2 = __float2bfloat16(v.z - __bfloat162float(h2));
    __nv_bfloat16 l3 = __float2bfloat16(v.w - __bfloat162float(h3));
    __nv_bfloat162* H2 = reinterpret_cast<__nv_bfloat162*>(Hi);
    __nv_bfloat162* L2 = reinterpret_cast<__nv_bfloat162*>(Lo);
    H2[2 * i + 0] = __halves2bfloat162(h0, h1);
    H2[2 * i + 1] = __halves2bfloat162(h2, h3);
    L2[2 * i + 0] = __halves2bfloat162(l0, l1);
    L2[2 * i + 1] = __halves2bfloat162(l2, l3);
}

// W[K][N] fp32 -> T[N][K] bf16 hi/lo (transpose + split)
__global__ __launch_bounds__(256) void transpose_split_kernel(
    const float* __restrict__ W,
    __nv_bfloat16* __restrict__ Thi, __nv_bfloat16* __restrict__ Tlo)
{
    __shared__ float tile[32][33];
    int tx = threadIdx.x, ty = threadIdx.y;
    int n0 = blockIdx.x * 32, k0 = blockIdx.y * 32;
#pragma unroll
    for (int i = 0; i < 32; i += 8)
        tile[ty + i][tx] = W[(size_t)(k0 + ty + i) * D_MODEL + n0 + tx];
    __syncthreads();
#pragma unroll
    for (int i = 0; i < 32; i += 8) {
        float v = tile[tx][ty + i];
        __nv_bfloat16 h = __float2bfloat16(v);
        __nv_bfloat16 l = __float2bfloat16(v - __bfloat162float(h));
        size_t o = (size_t)(n0 + ty + i) * D_MODEL + k0 + tx;
        Thi[o] = h; Tlo[o] = l;
    }
}

// ===========================================================================
// HMMA bf16-split GEMM: C[M,N] = A[M,K] @ Bt[N,K]^T + bias
// Output either fp32 (Cf) or bf16 hi/lo pair (Chi/Clo).
// ===========================================================================
#define GBM 128
#define GBN 128
#define GBK 64
#define TILE16K 16384
#define STAGEB (4 * TILE16K)          // Ahi,Alo,Bhi,Blo  = 64 KB
#define GEMM_SMEM (2 * STAGEB)        // 128 KB

__global__ __launch_bounds__(256, 1)
void gemm_hmma(const __nv_bfloat16* __restrict__ Ahi, const __nv_bfloat16* __restrict__ Alo,
               const __nv_bfloat16* __restrict__ Bhi, const __nv_bfloat16* __restrict__ Blo,
               const float* __restrict__ bias, float* __restrict__ Cf,
               __nv_bfloat16* __restrict__ Chi, __nv_bfloat16* __restrict__ Clo)
{
    extern __shared__ char smem[];
    const uint32_t sb = smem_to_u32(smem);
    const int tid  = threadIdx.x;
    const int lane = tid & 31;
    const int wid  = tid >> 5;
    const int wm   = wid >> 2;
    const int wn   = wid & 3;
    const int bm   = blockIdx.y * GBM;
    const int bn   = blockIdx.x * GBN;

    const char* pAh = reinterpret_cast<const char*>(Ahi);
    const char* pAl = reinterpret_cast<const char*>(Alo);
    const char* pBh = reinterpret_cast<const char*>(Bhi);
    const char* pBl = reinterpret_cast<const char*>(Blo);

    const int frA  = wm * 64 + (lane & 15);
    const int frB  = wn * 32 + (lane & 15);
    const int fch  = lane >> 4;
    const int a7   = frA & 7;
    const int b7   = frB & 7;

    float acc[4][4][4];
#pragma unroll
    for (int mt = 0; mt < 4; mt++)
#pragma unroll
        for (int nt = 0; nt < 4; nt++)
#pragma unroll
            for (int j = 0; j < 4; j++) acc[mt][nt][j] = 0.f;

    {
        const int k0 = 0;
#pragma unroll
        for (int it = 0; it < 4; it++) {
            int idx = it * 256 + tid;
            int r = idx >> 3, ch = idx & 7;
            uint32_t soff = r * 128 + ((ch ^ (r & 7)) << 4);
            size_t goA = (((size_t)(bm + r) << 10) + k0 + ch * 8) * 2;
            size_t goB = (((size_t)(bn + r) << 10) + k0 + ch * 8) * 2;
            cp16(sb + soff,                pAh + goA);
            cp16(sb + TILE16K + soff,      pAl + goA);
            cp16(sb + 2 * TILE16K + soff,  pBh + goB);
            cp16(sb + 3 * TILE16K + soff,  pBl + goB);
        }
        cp_commit();
    }

    for (int c = 0; c < D_MODEL / GBK; c++) {
        cp_wait_all();
        __syncthreads();

        if (c + 1 < D_MODEL / GBK) {
            const int k0 = (c + 1) * GBK;
            const uint32_t sdst = sb + ((c + 1) & 1) * STAGEB;
#pragma unroll
            for (int it = 0; it < 4; it++) {
                int idx = it * 256 + tid;
                int r = idx >> 3, ch = idx & 7;
                uint32_t soff = r * 128 + ((ch ^ (r & 7)) << 4);
                size_t goA = (((size_t)(bm + r) << 10) + k0 + ch * 8) * 2;
                size_t goB = (((size_t)(bn + r) << 10) + k0 + ch * 8) * 2;
                cp16(sdst + soff,               pAh + goA);
                cp16(sdst + TILE16K + soff,     pAl + goA);
                cp16(sdst + 2 * TILE16K + soff, pBh + goB);
                cp16(sdst + 3 * TILE16K + soff, pBl + goB);
            }
        }
        cp_commit();

        const uint32_t sA = sb + (c & 1) * STAGEB;
#pragma unroll
        for (int ks = 0; ks < 4; ks++) {
            uint32_t ah[4][4], al[4][4], bh[2][4], bl[2][4];
#pragma unroll
            for (int mt = 0; mt < 4; mt++) {
                uint32_t addr = sA + (uint32_t)(frA + mt * 16) * 128 +
                                ((uint32_t)((ks * 2 + fch) ^ a7) << 4);
                ldsm_x4(ah[mt], addr);
                ldsm_x4(al[mt], addr + TILE16K);
            }
#pragma unroll
            for (int bt = 0; bt < 2; bt++) {
                uint32_t addr = sA + 2 * TILE16K + (uint32_t)(frB + bt * 16) * 128 +
                                ((uint32_t)((ks * 2 + fch) ^ b7) << 4);
                ldsm_x4(bh[bt], addr);
                ldsm_x4(bl[bt], addr + TILE16K);
            }
#pragma unroll
            for (int mt = 0; mt < 4; mt++) {
#pragma unroll
                for (int nt = 0; nt < 4; nt++) {
                    const int bt = nt >> 1, wq = nt & 1;
                    mma_bf16(acc[mt][nt], ah[mt], bh[bt][wq], bh[bt][wq + 2]);
                    mma_bf16(acc[mt][nt], ah[mt], bl[bt][wq], bl[bt][wq + 2]);
                    mma_bf16(acc[mt][nt], al[mt], bh[bt][wq], bh[bt][wq + 2]);
                }
            }
        }
        __syncthreads();
    }

    const int row0 = bm + wm * 64 + (lane >> 2);
    const int col0 = bn + wn * 32 + (lane & 3) * 2;
#pragma unroll
    for (int mt = 0; mt < 4; mt++) {
#pragma unroll
        for (int nt = 0; nt < 4; nt++) {
            const int r = row0 + mt * 16;
            const int cc = col0 + nt * 8;
            float2 bv = *reinterpret_cast<const float2*>(bias + cc);
            float v0 = acc[mt][nt][0] + bv.x, v1 = acc[mt][nt][1] + bv.y;
            float v2 = acc[mt][nt][2] + bv.x, v3 = acc[mt][nt][3] + bv.y;
            if (Cf) {
                *reinterpret_cast<float2*>(Cf + (size_t)r * D_MODEL + cc) =
                    make_float2(v0, v1);
                *reinterpret_cast<float2*>(Cf + (size_t)(r + 8) * D_MODEL + cc) =
                    make_float2(v2, v3);
            } else {
                __nv_bfloat16 h0 = __float2bfloat16(v0), h1 = __float2bfloat16(v1);
                __nv_bfloat16 h2 = __float2bfloat16(v2), h3 = __float2bfloat16(v3);
                __nv_bfloat16 l0 = __float2bfloat16(v0 - __bfloat162float(h0));
                __nv_bfloat16 l1 = __float2bfloat16(v1 - __bfloat162float(h1));
                __nv_bfloat16 l2 = __float2bfloat16(v2 - __bfloat162float(h2));
                __nv_bfloat16 l3 = __float2bfloat16(v3 - __bfloat162float(h3));
                *reinterpret_cast<__nv_bfloat162*>(Chi + (size_t)r * D_MODEL + cc) =
                    __halves2bfloat162(h0, h1);
                *reinterpret_cast<__nv_bfloat162*>(Clo + (size_t)r * D_MODEL + cc) =
                    __halves2bfloat162(l0, l1);
                *reinterpret_cast<__nv_bfloat162*>(Chi + (size_t)(r + 8) * D_MODEL + cc) =
                    __halves2bfloat162(h2, h3);
                *reinterpret_cast<__nv_bfloat162*>(Clo + (size_t)(r + 8) * D_MODEL + cc) =
                    __halves2bfloat162(l2, l3);
            }
        }
    }
}

// ===========================================================================
// HMMA causal attention. Block = (b,h,64-row q-tile), 128 threads (4 warps).
// S = QK^T via 3-MMA bf16 split; exp in registers; P split hi/lo in regs;
// ctx = Phi@Vhi + Plo@Vhi + Phi@Vlo. Unnormalized P written to attn;
// row reciprocals exported to g_inv for the separate attn_finish kernel.
// Q tile parked in stage-1's buffer (frags extracted before stage 1 is
// written) -> smem 65 KB -> 3 CTAs/SM.
// ===========================================================================
#define ATT_STG 32768                 // Khi 8K + Klo 8K + Vhi 8K + Vlo 8K
#define ATT_SMEM (2 * ATT_STG + 512)  // 66048

__global__ __launch_bounds__(128, 3)
void attn_hmma(const __nv_bfloat16* __restrict__ Qhi, const __nv_bfloat16* __restrict__ Qlo,
               const __nv_bfloat16* __restrict__ Khi, const __nv_bfloat16* __restrict__ Klo,
               const __nv_bfloat16* __restrict__ Vhi, const __nv_bfloat16* __restrict__ Vlo,
               float* __restrict__ attn, float* __restrict__ rowinv,
               __nv_bfloat16* __restrict__ Chi, __nv_bfloat16* __restrict__ Clo)
{
    extern __shared__ char smem[];
    const uint32_t sb = smem_to_u32(smem);
    const uint32_t sQ = sb + ATT_STG;             // Q parked in stage 1
    float* sRow = reinterpret_cast<float*>(smem + 2 * ATT_STG);
    float* sInv = sRow + 64;

    const int tid  = threadIdx.x;
    const int lane = tid & 31;
    const int w    = tid >> 5;
    const int qt   = (int)gridDim.x - 1 - (int)blockIdx.x;   // largest first
    const int bh   = blockIdx.y;
    const int h    = bh & (NUM_HEADS - 1);
    const int b    = bh >> 4;
    const int qbase = qt * 64;

    const char* pQh = reinterpret_cast<const char*>(Qhi);
    const char* pQl = reinterpret_cast<const char*>(Qlo);
    const char* pKh = reinterpret_cast<const char*>(Khi);
    const char* pKl = reinterpret_cast<const char*>(Klo);
    const char* pVh = reinterpret_cast<const char*>(Vhi);
    const char* pVl = reinterpret_cast<const char*>(Vlo);

    const size_t rowStrideB = D_MODEL * 2;        // bytes per gmem row
    const size_t headOffB   = (size_t)h * DEPTH * 2;
    const size_t qRow0B = ((size_t)(b * SEQ + qbase)) * rowStrideB + headOffB;
    const size_t kRow0B = ((size_t)(b * SEQ)) * rowStrideB + headOffB;

    // ---- prologue: Q tile (into stage 1) + chunk 0 (into stage 0) ----
#pragma unroll
    for (int it = 0; it < 4; it++) {
        int idx = it * 128 + tid;                 // 0..511
        int r = idx >> 3, ch = idx & 7;
        uint32_t soff = r * 128 + ((ch ^ (r & 7)) << 4);
        size_t go = qRow0B + (size_t)r * rowStrideB + ch * 16;
        cp16(sQ + soff,        pQh + go);
        cp16(sQ + 8192 + soff, pQl + go);
        size_t gk = kRow0B + (size_t)r * rowStrideB + ch * 16;   // chunk 0
        cp16(sb + soff,         pKh + gk);
        cp16(sb + 8192 + soff,  pKl + gk);
        cp16(sb + 16384 + soff, pVh + gk);
        cp16(sb + 24576 + soff, pVl + gk);
    }
    cp_commit();
    cp_wait_all();
    __syncthreads();

    // ---- Q fragments (registers; stage 1 is free after this) ----
    uint32_t QAh[4][4], QAl[4][4];
    {
        const int qr = w * 16 + (lane & 15);
        const int q7 = qr & 7;
#pragma unroll
        for (int ks = 0; ks < 4; ks++) {
            uint32_t addr = sQ + (uint32_t)qr * 128 +
                            ((uint32_t)((ks * 2 + (lane >> 4)) ^ q7) << 4);
            ldsm_x4(QAh[ks], addr);
            ldsm_x4(QAl[ks], addr + 8192);
        }
    }
    __syncthreads();   // all warps done reading Q before stage 1 is overwritten

    float CT[8][4];
#pragma unroll
    for (int nt = 0; nt < 8; nt++)
#pragma unroll
        for (int j = 0; j < 4; j++) CT[nt][j] = 0.f;

    float rs0 = 0.f, rs1 = 0.f;
    const int rl = (lane >> 2);                   // 0..7
    const int tileRowLo = w * 16 + rl;            // 0..63 within q tile
    const int tileRowHi = tileRowLo + 8;
    const int colq = 2 * (lane & 3);              // 0..6 within 8-wide tile

    for (int c = 0; c <= qt; c++) {
        const int sp = c & 1;
        const uint32_t stb = sb + sp * ATT_STG;

        if (c < qt) {
            const uint32_t sdst = sb + (sp ^ 1) * ATT_STG;
            const size_t kRowB = kRow0B + (size_t)(c + 1) * 64 * rowStrideB;
#pragma unroll
            for (int it = 0; it < 4; it++) {
                int idx = it * 128 + tid;
                int r = idx >> 3, ch = idx & 7;
                uint32_t soff = r * 128 + ((ch ^ (r & 7)) << 4);
                size_t gk = kRowB + (size_t)r * rowStrideB + ch * 16;
                cp16(sdst + soff,         pKh + gk);
                cp16(sdst + 8192 + soff,  pKl + gk);
                cp16(sdst + 16384 + soff, pVh + gk);
                cp16(sdst + 24576 + soff, pVl + gk);
            }
        }
        cp_commit();

        // ---- S = Q @ K^T (3-MMA split), per-g LDSM->MMA for low reg live ----
        float S[8][4];
#pragma unroll
        for (int nt = 0; nt < 8; nt++)
#pragma unroll
            for (int j = 0; j < 4; j++) S[nt][j] = 0.f;

#pragma unroll
        for (int ks = 0; ks < 4; ks++) {
#pragma unroll
            for (int g = 0; g < 4; g++) {
                const int kr = g * 16 + (lane & 15);
                uint32_t addr = stb + (uint32_t)kr * 128 +
                                ((uint32_t)((ks * 2 + (lane >> 4)) ^ (kr & 7)) << 4);
                uint32_t kbh[4], kbl[4];
                ldsm_x4(kbh, addr);
                ldsm_x4(kbl, addr + 8192);
#pragma unroll
                for (int sub = 0; sub < 2; sub++) {
                    const int nt = 2 * g + sub;
                    mma_bf16(S[nt], QAh[ks], kbh[sub], kbh[sub + 2]);
                    mma_bf16(S[nt], QAh[ks], kbl[sub], kbl[sub + 2]);
                    mma_bf16(S[nt], QAl[ks], kbh[sub], kbh[sub + 2]);
                }
            }
        }

        // ---- exp, causal mask, attn store (unnormalized), row sums ----
        const int kb = c * 64;
        const bool diag = (c == qt);
        const size_t aRowLo = ((size_t)bh * SEQ + qbase + tileRowLo) * SEQ + kb;
        const size_t aRowHi = aRowLo + (size_t)8 * SEQ;
#pragma unroll
        for (int nt = 0; nt < 8; nt++) {
            const int tcol = nt * 8 + colq;
            float p0 = __expf(S[nt][0] * 0.125f);
            float p1 = __expf(S[nt][1] * 0.125f);
            float p2 = __expf(S[nt][2] * 0.125f);
            float p3 = __expf(S[nt][3] * 0.125f);
            if (diag) {
                if (tcol     > tileRowLo) p0 = 0.f;
                if (tcol + 1 > tileRowLo) p1 = 0.f;
                if (tcol     > tileRowHi) p2 = 0.f;
                if (tcol + 1 > tileRowHi) p3 = 0.f;
            }
            rs0 += p0 + p1;
            rs1 += p2 + p3;
            S[nt][0] = p0; S[nt][1] = p1; S[nt][2] = p2; S[nt][3] = p3;
            if (attn) {
                *reinterpret_cast<float2*>(attn + aRowLo + tcol) = make_float2(p0, p1);
                *reinterpret_cast<float2*>(attn + aRowHi + tcol) = make_float2(p2, p3);
            }
        }

        // ---- split P hi/lo, ctx += Phi@Vhi + Plo@Vhi + Phi@Vlo ----
#pragma unroll
        for (int ks = 0; ks < 4; ks++) {
            uint32_t PAh[4], PAl[4];
#pragma unroll
            for (int half = 0; half < 2; half++) {
                const float* sv = S[2 * ks + half];
#pragma unroll
                for (int pr = 0; pr < 2; pr++) {
                    float x0 = sv[2 * pr], x1 = sv[2 * pr + 1];
                    __nv_bfloat16 hh0 = __float2bfloat16(x0);
                    __nv_bfloat16 hh1 = __float2bfloat16(x1);
                    float r0f = x0 - __bfloat162float(hh0);
                    float r1f = x1 - __bfloat162float(hh1);
                    __nv_bfloat162 th = __halves2bfloat162(hh0, hh1);
                    __nv_bfloat162 tl = __halves2bfloat162(
                        __float2bfloat16(r0f), __float2bfloat16(r1f));
                    PAh[2 * half + pr] = *reinterpret_cast<uint32_t*>(&th);
                    PAl[2 * half + pr] = *reinterpret_cast<uint32_t*>(&tl);
                }
            }
#pragma unroll
            for (int g = 0; g < 4; g++) {
                const int vr = ks * 16 + (lane & 15);
                uint32_t addr = stb + 16384 + (uint32_t)vr * 128 +
                                ((uint32_t)((2 * g + (lane >> 4)) ^ (vr & 7)) << 4);
                uint32_t vbh[4], vbl[4];
                ldsm_x4_t(vbh, addr);
                ldsm_x4_t(vbl, addr + 8192);
                mma_bf16(CT[2 * g],     PAh, vbh[0], vbh[1]);
                mma_bf16(CT[2 * g],     PAl, vbh[0], vbh[1]);
                mma_bf16(CT[2 * g],     PAh, vbl[0], vbl[1]);
                mma_bf16(CT[2 * g + 1], PAh, vbh[2], vbh[3]);
                mma_bf16(CT[2 * g + 1], PAl, vbh[2], vbh[3]);
                mma_bf16(CT[2 * g + 1], PAh, vbl[2], vbl[3]);
            }
        }

        if (c < qt) {
            cp_wait_all();
            __syncthreads();
        }
    }

    // ---- row sums -> reciprocals (smem + gmem export) ----
    rs0 += __shfl_xor_sync(0xFFFFFFFFu, rs0, 1);
    rs0 += __shfl_xor_sync(0xFFFFFFFFu, rs0, 2);
    rs1 += __shfl_xor_sync(0xFFFFFFFFu, rs1, 1);
    rs1 += __shfl_xor_sync(0xFFFFFFFFu, rs1, 2);
    if ((lane & 3) == 0) {
        sRow[tileRowLo] = rs0;
        sRow[tileRowHi] = rs1;
    }
    __syncthreads();
    if (tid < 64) {
        float iv = 1.0f / sRow[tid];
        sInv[tid] = iv;
        rowinv[(size_t)bh * SEQ + qbase + tid] = iv;
    }
    __syncthreads();

    // ---- normalized ctx -> bf16 hi/lo ----
    {
        const float inv0 = sInv[tileRowLo];
        const float inv1 = sInv[tileRowHi];
        const size_t cRowLo = ((size_t)(b * SEQ + qbase + tileRowLo)) * D_MODEL + h * DEPTH;
        const size_t cRowHi = cRowLo + (size_t)8 * D_MODEL;
#pragma unroll
        for (int nt = 0; nt < 8; nt++) {
            const int d = nt * 8 + colq;
            float v0 = CT[nt][0] * inv0, v1 = CT[nt][1] * inv0;
            float v2 = CT[nt][2] * inv1, v3 = CT[nt][3] * inv1;
            __nv_bfloat16 h0 = __float2bfloat16(v0), h1 = __float2bfloat16(v1);
            __nv_bfloat16 h2 = __float2bfloat16(v2), h3 = __float2bfloat16(v3);
            __nv_bfloat16 l0 = __float2bfloat16(v0 - __bfloat162float(h0));
            __nv_bfloat16 l1 = __float2bfloat16(v1 - __bfloat162float(h1));
            __nv_bfloat16 l2 = __float2bfloat16(v2 - __bfloat162float(h2));
            __nv_bfloat16 l3 = __float2bfloat16(v3 - __bfloat162float(h3));
            *reinterpret_cast<__nv_bfloat162*>(Chi + cRowLo + d) = __halves2bfloat162(h0, h1);
            *reinterpret_cast<__nv_bfloat162*>(Clo + cRowLo + d) = __halves2bfloat162(l0, l1);
            *reinterpret_cast<__nv_bfloat162*>(Chi + cRowHi + d) = __halves2bfloat162(h2, h3);
            *reinterpret_cast<__nv_bfloat162*>(Clo + cRowHi + d) = __halves2bfloat162(l2, l3);
        }
    }
}

// ===========================================================================
// attn_finish: one block per attn row. Rescales the valid (lower-triangle)
// region by the row reciprocal; writes zeros above the diagonal w/o reading.
// ===========================================================================
__global__ __launch_bounds__(128)
void attn_finish(const float* __restrict__ rowinv, float* __restrict__ attn)
{
    const int row = blockIdx.x;                   // bh*SEQ + q
    const int q   = row & (SEQ - 1);
    const float iv = rowinv[row];
    float* base = attn + (size_t)row * SEQ;
    const int nk = q + 1;
#pragma unroll
    for (int it = 0; it < 4; it++) {
        const int col = (threadIdx.x + it * 128) * 4;
        float4* p = reinterpret_cast<float4*>(base + col);
        if (col + 4 <= nk) {
            float4 v = *p;
            v.x *= iv; v.y *= iv; v.z *= iv; v.w *= iv;
            *p = v;
        } else if (col >= nk) {
            *p = make_float4(0.f, 0.f, 0.f, 0.f);
        } else {
            float4 v = *p;
            v.x = (col + 0 < nk) ? v.x * iv : 0.f;
            v.y = (col + 1 < nk) ? v.y * iv : 0.f;
            v.z = (col + 2 < nk) ? v.z * iv : 0.f;
            v.w = (col + 3 < nk) ? v.w * iv : 0.f;
            *p = v;
        }
    }
}

// ---------------------------------------------------------------------------
extern "C" void kernel_launch(void* const* d_in, const int* in_sizes, int n_in,
                              void* d_out, int out_size)
{
    const float* q  = (const float*)d_in[0];
    const float* k  = (const float*)d_in[1];
    const float* v  = (const float*)d_in[2];
    const float* wq = (const float*)d_in[4];
    const float* bq = (const float*)d_in[5];
    const float* wk = (const float*)d_in[6];
    const float* bk = (const float*)d_in[7];
    const float* wv = (const float*)d_in[8];
    const float* bv = (const float*)d_in[9];
    const float* wo = (const float*)d_in[10];
    const float* bo = (const float*)d_in[11];

    float* out = (float*)d_out;
    float* attn = nullptr;
    if ((long long)out_size >= OUT_ELEMS + ATTN_ELEMS) attn = out + OUT_ELEMS;

    __nv_bfloat16 *Ahi, *Alo, *Whi, *Wlo, *Qhi, *Qlo, *Khi, *Klo, *Vhi, *Vlo, *Chi, *Clo;
    float* rinv;
    cudaGetSymbolAddress((void**)&Ahi, g_Ahi);
    cudaGetSymbolAddress((void**)&Alo, g_Alo);
    cudaGetSymbolAddress((void**)&Whi, g_Whi);
    cudaGetSymbolAddress((void**)&Wlo, g_Wlo);
    cudaGetSymbolAddress((void**)&Qhi, g_Qhi);
    cudaGetSymbolAddress((void**)&Qlo, g_Qlo);
    cudaGetSymbolAddress((void**)&Khi, g_Khi);
    cudaGetSymbolAddress((void**)&Klo, g_Klo);
    cudaGetSymbolAddress((void**)&Vhi, g_Vhi);
    cudaGetSymbolAddress((void**)&Vlo, g_Vlo);
    cudaGetSymbolAddress((void**)&Chi, g_Chi);
    cudaGetSymbolAddress((void**)&Clo, g_Clo);
    cudaGetSymbolAddress((void**)&rinv, g_inv);

    cudaFuncSetAttribute(gemm_hmma, cudaFuncAttributeMaxDynamicSharedMemorySize,
                         GEMM_SMEM);
    cudaFuncSetAttribute(attn_hmma, cudaFuncAttributeMaxDynamicSharedMemorySize,
                         ATT_SMEM);

    const int splitBlocks = (MTOT * D_MODEL / 4) / 256;   // 4096
    dim3 tgrid(D_MODEL / 32, D_MODEL / 32);               // (32,32)
    dim3 tblock(32, 8);
    dim3 ggrid(D_MODEL / GBN, MTOT / GBM);                // (8, 32)

    split_kernel<<<splitBlocks, 256>>>(q, Ahi, Alo);
    transpose_split_kernel<<<tgrid, tblock>>>(wq, Whi, Wlo);
    gemm_hmma<<<ggrid, 256, GEMM_SMEM>>>(Ahi, Alo, Whi, Wlo, bq, nullptr, Qhi, Qlo);

    split_kernel<<<splitBlocks, 256>>>(k, Ahi, Alo);
    transpose_split_kernel<<<tgrid, tblock>>>(wk, Whi, Wlo);
    gemm_hmma<<<ggrid, 256, GEMM_SMEM>>>(Ahi, Alo, Whi, Wlo, bk, nullptr, Khi, Klo);

    split_kernel<<<splitBlocks, 256>>>(v, Ahi, Alo);
    transpose_split_kernel<<<tgrid, tblock>>>(wv, Whi, Wlo);
    gemm_hmma<<<ggrid, 256, GEMM_SMEM>>>(Ahi, Alo, Whi, Wlo, bv, nullptr, Vhi, Vlo);

    attn_hmma<<<dim3(SEQ / 64, BATCH * NUM_HEADS), 128, ATT_SMEM>>>(
        Qhi, Qlo, Khi, Klo, Vhi, Vlo, attn, rinv, Chi, Clo);

    if (attn) {
        attn_finish<<<BATCH * NUM_HEADS * SEQ, 128>>>(rinv, attn);
    }

    transpose_split_kernel<<<tgrid, tblock>>>(wo, Whi, Wlo);
    gemm_hmma<<<ggrid, 256, GEMM_SMEM>>>(Chi, Clo, Whi, Wlo, bo, out, nullptr, nullptr);
}

// round 17
// speedup vs baseline: 2.5806x; 1.0429x over previous
#include <cuda_runtime.h>
#include <cuda_bf16.h>
#include <cstdint>

#define D_MODEL 1024
#define NUM_HEADS 16
#define DEPTH 64
#define BATCH 2
#define SEQ 2048
#define MTOT (BATCH * SEQ)            // 4096 rows
#define OUT_ELEMS ((long long)BATCH * SEQ * D_MODEL)          // 4,194,304
#define ATTN_ELEMS ((long long)BATCH * NUM_HEADS * SEQ * SEQ) // 134,217,728

// Scratch (no allocations allowed) — bf16 hi/lo pairs
__device__ __nv_bfloat16 g_Ahi3[3 * MTOT * D_MODEL];
__device__ __nv_bfloat16 g_Alo3[3 * MTOT * D_MODEL];
__device__ __nv_bfloat16 g_Whi3[3 * D_MODEL * D_MODEL];
__device__ __nv_bfloat16 g_Wlo3[3 * D_MODEL * D_MODEL];
__device__ __nv_bfloat16 g_Qhi[MTOT * D_MODEL];
__device__ __nv_bfloat16 g_Qlo[MTOT * D_MODEL];
__device__ __nv_bfloat16 g_Khi[MTOT * D_MODEL];
__device__ __nv_bfloat16 g_Klo[MTOT * D_MODEL];
__device__ __nv_bfloat16 g_Vhi[MTOT * D_MODEL];
__device__ __nv_bfloat16 g_Vlo[MTOT * D_MODEL];
__device__ __nv_bfloat16 g_Chi[MTOT * D_MODEL];
__device__ __nv_bfloat16 g_Clo[MTOT * D_MODEL];
__device__ float g_inv[BATCH * NUM_HEADS * SEQ];

// ===========================================================================
// Generic-PTX helpers (sm_80+: legal under the harness's compute_103 pass)
// ===========================================================================
__device__ __forceinline__ uint32_t smem_to_u32(const void* p) {
    uint32_t a;
    asm("{ .reg .u64 t; cvta.to.shared.u64 t, %1; cvt.u32.u64 %0, t; }"
        : "=r"(a) : "l"(p));
    return a;
}
__device__ __forceinline__ void cp16(uint32_t s, const void* g) {
    asm volatile("cp.async.cg.shared.global [%0], [%1], 16;"
                 :: "r"(s), "l"(g) : "memory");
}
__device__ __forceinline__ void cp_commit() {
    asm volatile("cp.async.commit_group;" ::: "memory");
}
__device__ __forceinline__ void cp_wait_all() {
    asm volatile("cp.async.wait_group 0;" ::: "memory");
}
__device__ __forceinline__ void ldsm_x4(uint32_t* r, uint32_t addr) {
    asm volatile("ldmatrix.sync.aligned.m8n8.x4.shared.b16 {%0,%1,%2,%3}, [%4];"
                 : "=r"(r[0]), "=r"(r[1]), "=r"(r[2]), "=r"(r[3]) : "r"(addr));
}
__device__ __forceinline__ void ldsm_x4_t(uint32_t* r, uint32_t addr) {
    asm volatile("ldmatrix.sync.aligned.m8n8.x4.trans.shared.b16 {%0,%1,%2,%3}, [%4];"
                 : "=r"(r[0]), "=r"(r[1]), "=r"(r[2]), "=r"(r[3]) : "r"(addr));
}
__device__ __forceinline__ void mma_bf16(float* c, const uint32_t* a,
                                         uint32_t b0, uint32_t b1) {
    asm volatile(
        "mma.sync.aligned.m16n8k16.row.col.f32.bf16.bf16.f32 "
        "{%0,%1,%2,%3}, {%4,%5,%6,%7}, {%8,%9}, {%0,%1,%2,%3};"
        : "+f"(c[0]), "+f"(c[1]), "+f"(c[2]), "+f"(c[3])
        : "r"(a[0]), "r"(a[1]), "r"(a[2]), "r"(a[3]), "r"(b0), "r"(b1));
}
__device__ __forceinline__ uint32_t packbf(float a, float b) {
    __nv_bfloat162 t = __halves2bfloat162(__float2bfloat16(a), __float2bfloat16(b));
    return *reinterpret_cast<uint32_t*>(&t);
}

// ===========================================================================
// Batched fp32 -> bf16 hi/lo split: 8 floats/thread, grid.z selects source.
// ===========================================================================
__global__ __launch_bounds__(256) void split3_kernel(
    const float* __restrict__ x0, const float* __restrict__ x1,
    const float* __restrict__ x2,
    __nv_bfloat16* __restrict__ Hi, __nv_bfloat16* __restrict__ Lo)
{
    const int z = blockIdx.z;
    const float* X = (z == 0) ? x0 : ((z == 1) ? x1 : x2);
    const size_t base8 = (size_t)z * (MTOT * D_MODEL / 8);
    const size_t i = blockIdx.x * 256 + threadIdx.x;     // 8-float unit
    float4 va = reinterpret_cast<const float4*>(X)[2 * i + 0];
    float4 vb = reinterpret_cast<const float4*>(X)[2 * i + 1];
    float hx[8] = {va.x, va.y, va.z, va.w, vb.x, vb.y, vb.z, vb.w};
    uint32_t hw[4], lw[4];
#pragma unroll
    for (int j = 0; j < 4; j++) {
        float a = hx[2 * j], b = hx[2 * j + 1];
        __nv_bfloat16 ha = __float2bfloat16(a), hb = __float2bfloat16(b);
        hw[j] = packbf(a, b);
        lw[j] = packbf(a - __bfloat162float(ha), b - __bfloat162float(hb));
    }
    uint4 hv = {hw[0], hw[1], hw[2], hw[3]};
    uint4 lv = {lw[0], lw[1], lw[2], lw[3]};
    reinterpret_cast<uint4*>(Hi)[base8 + i] = hv;
    reinterpret_cast<uint4*>(Lo)[base8 + i] = lv;
}

// W[K][N] fp32 -> T[N][K] bf16 hi/lo (transpose + split), grid.z selects W.
__global__ __launch_bounds__(256) void transpose3_kernel(
    const float* __restrict__ w0, const float* __restrict__ w1,
    const float* __restrict__ w2,
    __nv_bfloat16* __restrict__ Thi, __nv_bfloat16* __restrict__ Tlo)
{
    __shared__ float tile[32][33];
    const int z = blockIdx.z;
    const float* W = (z == 0) ? w0 : ((z == 1) ? w1 : w2);
    const size_t base = (size_t)z * D_MODEL * D_MODEL;
    int tx = threadIdx.x, ty = threadIdx.y;
    int n0 = blockIdx.x * 32, k0 = blockIdx.y * 32;
#pragma unroll
    for (int i = 0; i < 32; i += 8)
        tile[ty + i][tx] = W[(size_t)(k0 + ty + i) * D_MODEL + n0 + tx];
    __syncthreads();
#pragma unroll
    for (int i = 0; i < 32; i += 8) {
        float v = tile[tx][ty + i];
        __nv_bfloat16 h = __float2bfloat16(v);
        __nv_bfloat16 l = __float2bfloat16(v - __bfloat162float(h));
        size_t o = base + (size_t)(n0 + ty + i) * D_MODEL + k0 + tx;
        Thi[o] = h; Tlo[o] = l;
    }
}

// ===========================================================================
// HMMA bf16-split GEMM: C[M,N] = A[M,K] @ Bt[N,K]^T + bias
// Tile 128x256, BK=64, 8 warps (2x4), warp tile 64x64, double-buffered.
// grid.z batches independent GEMMs (A/W offset by z; bias/output selected).
// Output fp32 (Cf, z=0 only) or bf16 hi/lo pairs.
// ===========================================================================
#define GBM 128
#define GBN 256
#define GBK 64
#define A16K 16384
#define STAGEB 98304                  // Ahi16K+Alo16K+Bhi32K+Blo32K
#define GEMM_SMEM (2 * STAGEB)        // 192 KB

__global__ __launch_bounds__(256, 1)
void gemm_hmma(const __nv_bfloat16* __restrict__ Ahi3, const __nv_bfloat16* __restrict__ Alo3,
               const __nv_bfloat16* __restrict__ Whi3, const __nv_bfloat16* __restrict__ Wlo3,
               const float* __restrict__ b0, const float* __restrict__ b1,
               const float* __restrict__ b2,
               float* __restrict__ Cf,
               __nv_bfloat16* __restrict__ C0hi, __nv_bfloat16* __restrict__ C0lo,
               __nv_bfloat16* __restrict__ C1hi, __nv_bfloat16* __restrict__ C1lo,
               __nv_bfloat16* __restrict__ C2hi, __nv_bfloat16* __restrict__ C2lo)
{
    extern __shared__ char smem[];
    const uint32_t sb = smem_to_u32(smem);
    const int tid  = threadIdx.x;
    const int lane = tid & 31;
    const int wid  = tid >> 5;
    const int wm   = wid >> 2;          // 0..1
    const int wn   = wid & 3;           // 0..3
    const int bm   = blockIdx.y * GBM;
    const int bn   = blockIdx.x * GBN;
    const int z    = blockIdx.z;

    const float* bias = (z == 0) ? b0 : ((z == 1) ? b1 : b2);
    __nv_bfloat16* Chi = (z == 0) ? C0hi : ((z == 1) ? C1hi : C2hi);
    __nv_bfloat16* Clo = (z == 0) ? C0lo : ((z == 1) ? C1lo : C2lo);

    const char* pAh = reinterpret_cast<const char*>(Ahi3 + (size_t)z * MTOT * D_MODEL);
    const char* pAl = reinterpret_cast<const char*>(Alo3 + (size_t)z * MTOT * D_MODEL);
    const char* pBh = reinterpret_cast<const char*>(Whi3 + (size_t)z * D_MODEL * D_MODEL);
    const char* pBl = reinterpret_cast<const char*>(Wlo3 + (size_t)z * D_MODEL * D_MODEL);

    const int frA  = wm * 64 + (lane & 15);
    const int frB  = wn * 64 + (lane & 15);
    const int fch  = lane >> 4;
    const int a7   = frA & 7;
    const int b7   = frB & 7;

    float acc[4][8][4];
#pragma unroll
    for (int mt = 0; mt < 4; mt++)
#pragma unroll
        for (int nt = 0; nt < 8; nt++)
#pragma unroll
            for (int j = 0; j < 4; j++) acc[mt][nt][j] = 0.f;

    // prologue: chunk 0 into stage 0
    {
#pragma unroll
        for (int it = 0; it < 4; it++) {
            int idx = it * 256 + tid;
            int r = idx >> 3, ch = idx & 7;
            uint32_t soff = r * 128 + ((ch ^ (r & 7)) << 4);
            size_t goA = (((size_t)(bm + r) << 10) + ch * 8) * 2;
            cp16(sb + soff,        pAh + goA);
            cp16(sb + A16K + soff, pAl + goA);
        }
#pragma unroll
        for (int it = 0; it < 8; it++) {
            int idx = it * 256 + tid;
            int r = idx >> 3, ch = idx & 7;
            uint32_t soff = r * 128 + ((ch ^ (r & 7)) << 4);
            size_t goB = (((size_t)(bn + r) << 10) + ch * 8) * 2;
            cp16(sb + 2 * A16K + soff, pBh + goB);
            cp16(sb + 4 * A16K + soff, pBl + goB);
        }
        cp_commit();
    }

    for (int c = 0; c < D_MODEL / GBK; c++) {    // 16 chunks
        cp_wait_all();
        __syncthreads();

        if (c + 1 < D_MODEL / GBK) {
            const int k0 = (c + 1) * GBK;
            const uint32_t sdst = sb + ((c + 1) & 1) * STAGEB;
#pragma unroll
            for (int it = 0; it < 4; it++) {
                int idx = it * 256 + tid;
                int r = idx >> 3, ch = idx & 7;
                uint32_t soff = r * 128 + ((ch ^ (r & 7)) << 4);
                size_t goA = (((size_t)(bm + r) << 10) + k0 + ch * 8) * 2;
                cp16(sdst + soff,        pAh + goA);
                cp16(sdst + A16K + soff, pAl + goA);
            }
#pragma unroll
            for (int it = 0; it < 8; it++) {
                int idx = it * 256 + tid;
                int r = idx >> 3, ch = idx & 7;
                uint32_t soff = r * 128 + ((ch ^ (r & 7)) << 4);
                size_t goB = (((size_t)(bn + r) << 10) + k0 + ch * 8) * 2;
                cp16(sdst + 2 * A16K + soff, pBh + goB);
                cp16(sdst + 4 * A16K + soff, pBl + goB);
            }
        }
        cp_commit();

        const uint32_t sA = sb + (c & 1) * STAGEB;
#pragma unroll
        for (int ks = 0; ks < 4; ks++) {
            uint32_t ah[4][4], al[4][4];
#pragma unroll
            for (int mt = 0; mt < 4; mt++) {
                uint32_t addr = sA + (uint32_t)(frA + mt * 16) * 128 +
                                ((uint32_t)((ks * 2 + fch) ^ a7) << 4);
                ldsm_x4(ah[mt], addr);
                ldsm_x4(al[mt], addr + A16K);
            }
#pragma unroll
            for (int bt = 0; bt < 4; bt++) {
                uint32_t bh[4], bl[4];
                uint32_t addr = sA + 2 * A16K + (uint32_t)(frB + bt * 16) * 128 +
                                ((uint32_t)((ks * 2 + fch) ^ b7) << 4);
                ldsm_x4(bh, addr);
                ldsm_x4(bl, addr + 2 * A16K);
#pragma unroll
                for (int mt = 0; mt < 4; mt++) {
#pragma unroll
                    for (int sub = 0; sub < 2; sub++) {
                        const int nt = 2 * bt + sub;
                        mma_bf16(acc[mt][nt], ah[mt], bh[sub], bh[sub + 2]);
                        mma_bf16(acc[mt][nt], ah[mt], bl[sub], bl[sub + 2]);
                        mma_bf16(acc[mt][nt], al[mt], bh[sub], bh[sub + 2]);
                    }
                }
            }
        }
        __syncthreads();
    }

    const int row0 = bm + wm * 64 + (lane >> 2);
    const int col0 = bn + wn * 64 + (lane & 3) * 2;
#pragma unroll
    for (int mt = 0; mt < 4; mt++) {
#pragma unroll
        for (int nt = 0; nt < 8; nt++) {
            const int r = row0 + mt * 16;
            const int cc = col0 + nt * 8;
            float2 bv = *reinterpret_cast<const float2*>(bias + cc);
            float v0 = acc[mt][nt][0] + bv.x, v1 = acc[mt][nt][1] + bv.y;
            float v2 = acc[mt][nt][2] + bv.x, v3 = acc[mt][nt][3] + bv.y;
            if (Cf) {
                *reinterpret_cast<float2*>(Cf + (size_t)r * D_MODEL + cc) =
                    make_float2(v0, v1);
                *reinterpret_cast<float2*>(Cf + (size_t)(r + 8) * D_MODEL + cc) =
                    make_float2(v2, v3);
            } else {
                __nv_bfloat16 h0 = __float2bfloat16(v0), h1 = __float2bfloat16(v1);
                __nv_bfloat16 h2 = __float2bfloat16(v2), h3 = __float2bfloat16(v3);
                uint32_t hi01 = packbf(v0, v1), hi23 = packbf(v2, v3);
                uint32_t lo01 = packbf(v0 - __bfloat162float(h0), v1 - __bfloat162float(h1));
                uint32_t lo23 = packbf(v2 - __bfloat162float(h2), v3 - __bfloat162float(h3));
                *reinterpret_cast<uint32_t*>(Chi + (size_t)r * D_MODEL + cc) = hi01;
                *reinterpret_cast<uint32_t*>(Clo + (size_t)r * D_MODEL + cc) = lo01;
                *reinterpret_cast<uint32_t*>(Chi + (size_t)(r + 8) * D_MODEL + cc) = hi23;
                *reinterpret_cast<uint32_t*>(Clo + (size_t)(r + 8) * D_MODEL + cc) = lo23;
            }
        }
    }
}

// ===========================================================================
// HMMA causal attention (unchanged from R16 best).
// ===========================================================================
#define ATT_STG 32768                 // Khi 8K + Klo 8K + Vhi 8K + Vlo 8K
#define ATT_SMEM (2 * ATT_STG + 512)  // 66048

__global__ __launch_bounds__(128, 3)
void attn_hmma(const __nv_bfloat16* __restrict__ Qhi, const __nv_bfloat16* __restrict__ Qlo,
               const __nv_bfloat16* __restrict__ Khi, const __nv_bfloat16* __restrict__ Klo,
               const __nv_bfloat16* __restrict__ Vhi, const __nv_bfloat16* __restrict__ Vlo,
               float* __restrict__ attn, float* __restrict__ rowinv,
               __nv_bfloat16* __restrict__ Chi, __nv_bfloat16* __restrict__ Clo)
{
    extern __shared__ char smem[];
    const uint32_t sb = smem_to_u32(smem);
    const uint32_t sQ = sb + ATT_STG;             // Q parked in stage 1
    float* sRow = reinterpret_cast<float*>(smem + 2 * ATT_STG);
    float* sInv = sRow + 64;

    const int tid  = threadIdx.x;
    const int lane = tid & 31;
    const int w    = tid >> 5;
    const int qt   = (int)gridDim.x - 1 - (int)blockIdx.x;   // largest first
    const int bh   = blockIdx.y;
    const int h    = bh & (NUM_HEADS - 1);
    const int b    = bh >> 4;
    const int qbase = qt * 64;

    const char* pQh = reinterpret_cast<const char*>(Qhi);
    const char* pQl = reinterpret_cast<const char*>(Qlo);
    const char* pKh = reinterpret_cast<const char*>(Khi);
    const char* pKl = reinterpret_cast<const char*>(Klo);
    const char* pVh = reinterpret_cast<const char*>(Vhi);
    const char* pVl = reinterpret_cast<const char*>(Vlo);

    const size_t rowStrideB = D_MODEL * 2;        // bytes per gmem row
    const size_t headOffB   = (size_t)h * DEPTH * 2;
    const size_t qRow0B = ((size_t)(b * SEQ + qbase)) * rowStrideB + headOffB;
    const size_t kRow0B = ((size_t)(b * SEQ)) * rowStrideB + headOffB;

    // ---- prologue: Q tile (into stage 1) + chunk 0 (into stage 0) ----
#pragma unroll
    for (int it = 0; it < 4; it++) {
        int idx = it * 128 + tid;                 // 0..511
        int r = idx >> 3, ch = idx & 7;
        uint32_t soff = r * 128 + ((ch ^ (r & 7)) << 4);
        size_t go = qRow0B + (size_t)r * rowStrideB + ch * 16;
        cp16(sQ + soff,        pQh + go);
        cp16(sQ + 8192 + soff, pQl + go);
        size_t gk = kRow0B + (size_t)r * rowStrideB + ch * 16;   // chunk 0
        cp16(sb + soff,         pKh + gk);
        cp16(sb + 8192 + soff,  pKl + gk);
        cp16(sb + 16384 + soff, pVh + gk);
        cp16(sb + 24576 + soff, pVl + gk);
    }
    cp_commit();
    cp_wait_all();
    __syncthreads();

    // ---- Q fragments (registers; stage 1 is free after this) ----
    uint32_t QAh[4][4], QAl[4][4];
    {
        const int qr = w * 16 + (lane & 15);
        const int q7 = qr & 7;
#pragma unroll
        for (int ks = 0; ks < 4; ks++) {
            uint32_t addr = sQ + (uint32_t)qr * 128 +
                            ((uint32_t)((ks * 2 + (lane >> 4)) ^ q7) << 4);
            ldsm_x4(QAh[ks], addr);
            ldsm_x4(QAl[ks], addr + 8192);
        }
    }
    __syncthreads();   // all warps done reading Q before stage 1 is overwritten

    float CT[8][4];
#pragma unroll
    for (int nt = 0; nt < 8; nt++)
#pragma unroll
        for (int j = 0; j < 4; j++) CT[nt][j] = 0.f;

    float rs0 = 0.f, rs1 = 0.f;
    const int rl = (lane >> 2);                   // 0..7
    const int tileRowLo = w * 16 + rl;            // 0..63 within q tile
    const int tileRowHi = tileRowLo + 8;
    const int colq = 2 * (lane & 3);              // 0..6 within 8-wide tile

    for (int c = 0; c <= qt; c++) {
        const int sp = c & 1;
        const uint32_t stb = sb + sp * ATT_STG;

        if (c < qt) {
            const uint32_t sdst = sb + (sp ^ 1) * ATT_STG;
            const size_t kRowB = kRow0B + (size_t)(c + 1) * 64 * rowStrideB;
#pragma unroll
            for (int it = 0; it < 4; it++) {
                int idx = it * 128 + tid;
                int r = idx >> 3, ch = idx & 7;
                uint32_t soff = r * 128 + ((ch ^ (r & 7)) << 4);
                size_t gk = kRowB + (size_t)r * rowStrideB + ch * 16;
                cp16(sdst + soff,         pKh + gk);
                cp16(sdst + 8192 + soff,  pKl + gk);
                cp16(sdst + 16384 + soff, pVh + gk);
                cp16(sdst + 24576 + soff, pVl + gk);
            }
        }
        cp_commit();

        // ---- S = Q @ K^T (3-MMA split) ----
        float S[8][4];
#pragma unroll
        for (int nt = 0; nt < 8; nt++)
#pragma unroll
            for (int j = 0; j < 4; j++) S[nt][j] = 0.f;

#pragma unroll
        for (int ks = 0; ks < 4; ks++) {
#pragma unroll
            for (int g = 0; g < 4; g++) {
                const int kr = g * 16 + (lane & 15);
                uint32_t addr = stb + (uint32_t)kr * 128 +
                                ((uint32_t)((ks * 2 + (lane >> 4)) ^ (kr & 7)) << 4);
                uint32_t kbh[4], kbl[4];
                ldsm_x4(kbh, addr);
                ldsm_x4(kbl, addr + 8192);
#pragma unroll
                for (int sub = 0; sub < 2; sub++) {
                    const int nt = 2 * g + sub;
                    mma_bf16(S[nt], QAh[ks], kbh[sub], kbh[sub + 2]);
                    mma_bf16(S[nt], QAh[ks], kbl[sub], kbl[sub + 2]);
                    mma_bf16(S[nt], QAl[ks], kbh[sub], kbh[sub + 2]);
                }
            }
        }

        // ---- exp, causal mask, attn store (unnormalized), row sums ----
        const int kb = c * 64;
        const bool diag = (c == qt);
        const size_t aRowLo = ((size_t)bh * SEQ + qbase + tileRowLo) * SEQ + kb;
        const size_t aRowHi = aRowLo + (size_t)8 * SEQ;
#pragma unroll
        for (int nt = 0; nt < 8; nt++) {
            const int tcol = nt * 8 + colq;
            float p0 = __expf(S[nt][0] * 0.125f);
            float p1 = __expf(S[nt][1] * 0.125f);
            float p2 = __expf(S[nt][2] * 0.125f);
            float p3 = __expf(S[nt][3] * 0.125f);
            if (diag) {
                if (tcol     > tileRowLo) p0 = 0.f;
                if (tcol + 1 > tileRowLo) p1 = 0.f;
                if (tcol     > tileRowHi) p2 = 0.f;
                if (tcol + 1 > tileRowHi) p3 = 0.f;
            }
            rs0 += p0 + p1;
            rs1 += p2 + p3;
            S[nt][0] = p0; S[nt][1] = p1; S[nt][2] = p2; S[nt][3] = p3;
            if (attn) {
                *reinterpret_cast<float2*>(attn + aRowLo + tcol) = make_float2(p0, p1);
                *reinterpret_cast<float2*>(attn + aRowHi + tcol) = make_float2(p2, p3);
            }
        }

        // ---- split P hi/lo, ctx += Phi@Vhi + Plo@Vhi + Phi@Vlo ----
#pragma unroll
        for (int ks = 0; ks < 4; ks++) {
            uint32_t PAh[4], PAl[4];
#pragma unroll
            for (int half = 0; half < 2; half++) {
                const float* sv = S[2 * ks + half];
#pragma unroll
                for (int pr = 0; pr < 2; pr++) {
                    float x0 = sv[2 * pr], x1 = sv[2 * pr + 1];
                    __nv_bfloat16 hh0 = __float2bfloat16(x0);
                    __nv_bfloat16 hh1 = __float2bfloat16(x1);
                    PAh[2 * half + pr] = packbf(x0, x1);
                    PAl[2 * half + pr] = packbf(x0 - __bfloat162float(hh0),
                                                x1 - __bfloat162float(hh1));
                }
            }
#pragma unroll
            for (int g = 0; g < 4; g++) {
                const int vr = ks * 16 + (lane & 15);
                uint32_t addr = stb + 16384 + (uint32_t)vr * 128 +
                                ((uint32_t)((2 * g + (lane >> 4)) ^ (vr & 7)) << 4);
                uint32_t vbh[4], vbl[4];
                ldsm_x4_t(vbh, addr);
                ldsm_x4_t(vbl, addr + 8192);
                mma_bf16(CT[2 * g],     PAh, vbh[0], vbh[1]);
                mma_bf16(CT[2 * g],     PAl, vbh[0], vbh[1]);
                mma_bf16(CT[2 * g],     PAh, vbl[0], vbl[1]);
                mma_bf16(CT[2 * g + 1], PAh, vbh[2], vbh[3]);
                mma_bf16(CT[2 * g + 1], PAl, vbh[2], vbh[3]);
                mma_bf16(CT[2 * g + 1], PAh, vbl[2], vbl[3]);
            }
        }

        if (c < qt) {
            cp_wait_all();
            __syncthreads();
        }
    }

    // ---- row sums -> reciprocals (smem + gmem export) ----
    rs0 += __shfl_xor_sync(0xFFFFFFFFu, rs0, 1);
    rs0 += __shfl_xor_sync(0xFFFFFFFFu, rs0, 2);
    rs1 += __shfl_xor_sync(0xFFFFFFFFu, rs1, 1);
    rs1 += __shfl_xor_sync(0xFFFFFFFFu, rs1, 2);
    if ((lane & 3) == 0) {
        sRow[tileRowLo] = rs0;
        sRow[tileRowHi] = rs1;
    }
    __syncthreads();
    if (tid < 64) {
        float iv = 1.0f / sRow[tid];
        sInv[tid] = iv;
        rowinv[(size_t)bh * SEQ + qbase + tid] = iv;
    }
    __syncthreads();

    // ---- normalized ctx -> bf16 hi/lo ----
    {
        const float inv0 = sInv[tileRowLo];
        const float inv1 = sInv[tileRowHi];
        const size_t cRowLo = ((size_t)(b * SEQ + qbase + tileRowLo)) * D_MODEL + h * DEPTH;
        const size_t cRowHi = cRowLo + (size_t)8 * D_MODEL;
#pragma unroll
        for (int nt = 0; nt < 8; nt++) {
            const int d = nt * 8 + colq;
            float v0 = CT[nt][0] * inv0, v1 = CT[nt][1] * inv0;
            float v2 = CT[nt][2] * inv1, v3 = CT[nt][3] * inv1;
            __nv_bfloat16 h0 = __float2bfloat16(v0), h1 = __float2bfloat16(v1);
            __nv_bfloat16 h2 = __float2bfloat16(v2), h3 = __float2bfloat16(v3);
            *reinterpret_cast<uint32_t*>(Chi + cRowLo + d) = packbf(v0, v1);
            *reinterpret_cast<uint32_t*>(Clo + cRowLo + d) =
                packbf(v0 - __bfloat162float(h0), v1 - __bfloat162float(h1));
            *reinterpret_cast<uint32_t*>(Chi + cRowHi + d) = packbf(v2, v3);
            *reinterpret_cast<uint32_t*>(Clo + cRowHi + d) =
                packbf(v2 - __bfloat162float(h2), v3 - __bfloat162float(h3));
        }
    }
}

// ===========================================================================
// attn_finish: one block per attn row. Rescales the valid (lower-triangle)
// region by the row reciprocal; writes zeros above the diagonal w/o reading.
// ===========================================================================
__global__ __launch_bounds__(128)
void attn_finish(const float* __restrict__ rowinv, float* __restrict__ attn)
{
    const int row = blockIdx.x;                   // bh*SEQ + q
    const int q   = row & (SEQ - 1);
    const float iv = rowinv[row];
    float* base = attn + (size_t)row * SEQ;
    const int nk = q + 1;
#pragma unroll
    for (int it = 0; it < 4; it++) {
        const int col = (threadIdx.x + it * 128) * 4;
        float4* p = reinterpret_cast<float4*>(base + col);
        if (col + 4 <= nk) {
            float4 v = *p;
            v.x *= iv; v.y *= iv; v.z *= iv; v.w *= iv;
            *p = v;
        } else if (col >= nk) {
            *p = make_float4(0.f, 0.f, 0.f, 0.f);
        } else {
            float4 v = *p;
            v.x = (col + 0 < nk) ? v.x * iv : 0.f;
            v.y = (col + 1 < nk) ? v.y * iv : 0.f;
            v.z = (col + 2 < nk) ? v.z * iv : 0.f;
            v.w = (col + 3 < nk) ? v.w * iv : 0.f;
            *p = v;
        }
    }
}

// ---------------------------------------------------------------------------
extern "C" void kernel_launch(void* const* d_in, const int* in_sizes, int n_in,
                              void* d_out, int out_size)
{
    const float* q  = (const float*)d_in[0];
    const float* k  = (const float*)d_in[1];
    const float* v  = (const float*)d_in[2];
    const float* wq = (const float*)d_in[4];
    const float* bq = (const float*)d_in[5];
    const float* wk = (const float*)d_in[6];
    const float* bk = (const float*)d_in[7];
    const float* wv = (const float*)d_in[8];
    const float* bv = (const float*)d_in[9];
    const float* wo = (const float*)d_in[10];
    const float* bo = (const float*)d_in[11];

    float* out = (float*)d_out;
    float* attn = nullptr;
    if ((long long)out_size >= OUT_ELEMS + ATTN_ELEMS) attn = out + OUT_ELEMS;

    __nv_bfloat16 *Ahi3, *Alo3, *Whi3, *Wlo3, *Qhi, *Qlo, *Khi, *Klo, *Vhi, *Vlo, *Chi, *Clo;
    float* rinv;
    cudaGetSymbolAddress((void**)&Ahi3, g_Ahi3);
    cudaGetSymbolAddress((void**)&Alo3, g_Alo3);
    cudaGetSymbolAddress((void**)&Whi3, g_Whi3);
    cudaGetSymbolAddress((void**)&Wlo3, g_Wlo3);
    cudaGetSymbolAddress((void**)&Qhi, g_Qhi);
    cudaGetSymbolAddress((void**)&Qlo, g_Qlo);
    cudaGetSymbolAddress((void**)&Khi, g_Khi);
    cudaGetSymbolAddress((void**)&Klo, g_Klo);
    cudaGetSymbolAddress((void**)&Vhi, g_Vhi);
    cudaGetSymbolAddress((void**)&Vlo, g_Vlo);
    cudaGetSymbolAddress((void**)&Chi, g_Chi);
    cudaGetSymbolAddress((void**)&Clo, g_Clo);
    cudaGetSymbolAddress((void**)&rinv, g_inv);

    cudaFuncSetAttribute(gemm_hmma, cudaFuncAttributeMaxDynamicSharedMemorySize,
                         GEMM_SMEM);
    cudaFuncSetAttribute(attn_hmma, cudaFuncAttributeMaxDynamicSharedMemorySize,
                         ATT_SMEM);

    // ---- QKV path: batched split / transpose / GEMM ----
    split3_kernel<<<dim3(MTOT * D_MODEL / 8 / 256, 1, 3), 256>>>(q, k, v, Ahi3, Alo3);
    transpose3_kernel<<<dim3(32, 32, 3), dim3(32, 8)>>>(wq, wk, wv, Whi3, Wlo3);
    gemm_hmma<<<dim3(D_MODEL / GBN, MTOT / GBM, 3), 256, GEMM_SMEM>>>(
        Ahi3, Alo3, Whi3, Wlo3, bq, bk, bv, nullptr,
        Qhi, Qlo, Khi, Klo, Vhi, Vlo);

    // ---- attention ----
    attn_hmma<<<dim3(SEQ / 64, BATCH * NUM_HEADS), 128, ATT_SMEM>>>(
        Qhi, Qlo, Khi, Klo, Vhi, Vlo, attn, rinv, Chi, Clo);
    if (attn) {
        attn_finish<<<BATCH * NUM_HEADS * SEQ, 128>>>(rinv, attn);
    }

    // ---- output projection ----
    transpose3_kernel<<<dim3(32, 32, 1), dim3(32, 8)>>>(wo, wo, wo, Whi3, Wlo3);
    gemm_hmma<<<dim3(D_MODEL / GBN, MTOT / GBM, 1), 256, GEMM_SMEM>>>(
        Chi, Clo, Whi3, Wlo3, bo, bo, bo, out,
        nullptr, nullptr, nullptr, nullptr, nullptr, nullptr);
}